// round 9
// baseline (speedup 1.0000x reference)
#include <cuda_runtime.h>
#include <cstdint>

#define N_HEADS 4
#define OUTC 1024
#define NSLOPE 0.2f

#define MAXNX 9000
#define MAXNC 1000
#define MAXN  (MAXNX + MAXNC)
#define MAXE0 40000
#define MAXE  (MAXE0 + MAXN)

// ------------------------- static scratch (no allocs) -------------------------
__device__ float g_xin[MAXNX * 400];
__device__ float g_xh[MAXNX * 512];
__device__ float g_xc[MAXN * 1024];
__device__ float g_xl[MAXN * 4096];
__device__ float g_xr[MAXN * 4096];
__device__ float g_outm[MAXN * 1024];
__device__ float g_alpha[MAXE * N_HEADS];
__device__ float g_wbuf[1024 * 4096];
__device__ int   g_src[MAXE];
__device__ int   g_dst[MAXE];
__device__ int   g_deg[MAXN];
__device__ int   g_off[MAXN + 1];
__device__ int   g_cur[MAXN];
__device__ int   g_csr[MAXE];

// ------------------------- helpers -------------------------
__device__ __forceinline__ float tf32r(float x) {
    uint32_t r;
    asm("cvt.rna.tf32.f32 %0, %1;" : "=r"(r) : "f"(x));
    return __uint_as_float(r);
}
__device__ __forceinline__ void cp16(uint32_t saddr, const float* g, bool valid) {
    int sz = valid ? 16 : 0;
    asm volatile("cp.async.cg.shared.global [%0], [%1], 16, %2;\n"
                 :: "r"(saddr), "l"(g), "r"(sz));
}

// ------------------------- small utility kernels -------------------------
__global__ void zero_int2(int* a, int* b, int n) {
    int i = blockIdx.x * blockDim.x + threadIdx.x;
    if (i < n) { a[i] = 0; b[i] = 0; }
}
__global__ void copy_f4(const float4* __restrict__ s, float4* __restrict__ d, int n4) {
    int i = blockIdx.x * blockDim.x + threadIdx.x;
    if (i < n4) d[i] = s[i];
}
__global__ void round_tf32_copy4(const float4* __restrict__ a, float4* __restrict__ b, int n4) {
    int i = blockIdx.x * blockDim.x + threadIdx.x;
    if (i < n4) {
        float4 v = a[i];
        v.x = tf32r(v.x); v.y = tf32r(v.y); v.z = tf32r(v.z); v.w = tf32r(v.w);
        b[i] = v;
    }
}

// edge_index is int32 (JAX x64-disabled downcast)
__global__ void build_edges(const int* __restrict__ ei, int* __restrict__ src,
                            int* __restrict__ dst, int* __restrict__ deg, int E, int N) {
    int e = blockIdx.x * blockDim.x + threadIdx.x;
    int ET = E + N;
    if (e >= ET) return;
    int s, d;
    if (e < E) { s = ei[2 * e]; d = ei[2 * e + 1]; }
    else       { s = d = e - E; }
    src[e] = s; dst[e] = d;
    atomicAdd(&deg[d], 1);
}
__global__ void scan_excl(const int* __restrict__ deg, int* __restrict__ off, int n) {
    __shared__ int sh[1024];
    __shared__ int carry;
    if (threadIdx.x == 0) carry = 0;
    __syncthreads();
    for (int base = 0; base < n; base += 1024) {
        int i = base + threadIdx.x;
        int v = (i < n) ? deg[i] : 0;
        sh[threadIdx.x] = v;
        __syncthreads();
        #pragma unroll
        for (int ofs = 1; ofs < 1024; ofs <<= 1) {
            int t = (threadIdx.x >= ofs) ? sh[threadIdx.x - ofs] : 0;
            __syncthreads();
            sh[threadIdx.x] += t;
            __syncthreads();
        }
        if (i < n) off[i] = carry + sh[threadIdx.x] - v;
        __syncthreads();
        if (threadIdx.x == 1023) carry += sh[1023];
        __syncthreads();
    }
    if (threadIdx.x == 0) off[n] = carry;
}
__global__ void fill_csr(const int* __restrict__ dst, const int* __restrict__ off,
                         int* __restrict__ cur, int* __restrict__ csr, int ET) {
    int e = blockIdx.x * blockDim.x + threadIdx.x;
    if (e >= ET) return;
    int d = dst[e];
    int p = off[d] + atomicAdd(&cur[d], 1);
    csr[p] = e;
}

// ===================== mma.sync tf32 GEMM, fragment double-buffered =====================
// 128x256x32 CTA tile, 8 warps of 64x64, 3-stage cp.async smem pipeline,
// register double-buffer of A/B fragments across the 4 kk-steps.
#define BM 128
#define BN 256
#define BK 32
#define LDA 36            // %32==4 -> conflict-free A frag reads
#define LDB 260           // %32==4 -> conflict-free B frag reads
#define ASTAGE (BM * LDA)
#define BSTAGE (BK * LDB)
#define SSTAGE (ASTAGE + BSTAGE)
#define NSTAGES 3
#define GEMM_SMEM_BYTES (SSTAGE * NSTAGES * 4)

__device__ __forceinline__ void mma8(float* c, const uint32_t* a, uint32_t b0, uint32_t b1) {
    asm volatile(
        "mma.sync.aligned.m16n8k8.row.col.f32.tf32.tf32.f32 "
        "{%0,%1,%2,%3}, {%4,%5,%6,%7}, {%8,%9}, {%0,%1,%2,%3};\n"
        : "+f"(c[0]), "+f"(c[1]), "+f"(c[2]), "+f"(c[3])
        : "r"(a[0]), "r"(a[1]), "r"(a[2]), "r"(a[3]), "r"(b0), "r"(b1));
}

template <bool RELU, bool ROUND>
__global__ __launch_bounds__(256)
void gemm_tf32(const float* __restrict__ A, const float* __restrict__ B,
               const float* __restrict__ bias, float* __restrict__ C,
               int M, int N, int K) {
    extern __shared__ float sm[];
    int tid  = threadIdx.x;
    int warp = tid >> 5;
    int lane = tid & 31;
    int g = lane >> 2;        // 0..7
    int t = lane & 3;         // 0..3
    int wm = warp >> 2;       // 0..1
    int wn = warp & 3;        // 0..3
    int mbase = wm * 64;
    int nbase = wn * 64;
    int am0 = blockIdx.y * BM;
    int bn0 = blockIdx.x * BN;
    int NIT = (K + BK - 1) / BK;

    float acc[4][8][4];
    #pragma unroll
    for (int i = 0; i < 4; i++)
        #pragma unroll
        for (int j = 0; j < 8; j++)
            #pragma unroll
            for (int k = 0; k < 4; k++) acc[i][j][k] = 0.0f;

    uint32_t smbase = (uint32_t)__cvta_generic_to_shared(sm);

    auto load_stage = [&](int it, int st) {
        int kt = it * BK;
        uint32_t as = smbase + (uint32_t)(st * SSTAGE) * 4u;
        uint32_t bs = as + (uint32_t)ASTAGE * 4u;
        #pragma unroll
        for (int i = 0; i < 4; i++) {          // A: 128 rows x 8 float4
            int idx = tid + i * 256;
            int r  = idx >> 3;
            int c4 = (idx & 7) * 4;
            bool v = (am0 + r < M) && (kt + c4 + 4 <= K);
            const float* gp = A + (size_t)(v ? (am0 + r) : 0) * K + (v ? (kt + c4) : 0);
            cp16(as + (uint32_t)(r * LDA + c4) * 4u, gp, v);
        }
        #pragma unroll
        for (int i = 0; i < 8; i++) {          // B: 32 rows x 64 float4
            int idx = tid + i * 256;
            int r  = idx >> 6;
            int c4 = (idx & 63) * 4;
            bool v = (kt + r < K) && (bn0 + c4 + 4 <= N);
            const float* gp = B + (size_t)(v ? (kt + r) : 0) * N + (v ? (bn0 + c4) : 0);
            cp16(bs + (uint32_t)(r * LDB + c4) * 4u, gp, v);
        }
        asm volatile("cp.async.commit_group;\n");
    };

    uint32_t af[2][4][4], bf[2][8][2];

    auto lda_frags = [&](const float* As, int kk, uint32_t (&a)[4][4]) {
        #pragma unroll
        for (int mf = 0; mf < 4; mf++) {
            int r = mbase + mf * 16 + g;
            a[mf][0] = __float_as_uint(As[r * LDA + kk + t]);
            a[mf][1] = __float_as_uint(As[(r + 8) * LDA + kk + t]);
            a[mf][2] = __float_as_uint(As[r * LDA + kk + t + 4]);
            a[mf][3] = __float_as_uint(As[(r + 8) * LDA + kk + t + 4]);
        }
    };
    auto ldb_frags = [&](const float* Bs, int kk, uint32_t (&b)[8][2]) {
        #pragma unroll
        for (int nf = 0; nf < 8; nf++) {
            int ccol = nbase + nf * 8 + g;
            b[nf][0] = __float_as_uint(Bs[(kk + t) * LDB + ccol]);
            b[nf][1] = __float_as_uint(Bs[(kk + t + 4) * LDB + ccol]);
        }
    };

    load_stage(0, 0);
    if (NIT > 1) load_stage(1, 1);

    for (int it = 0; it < NIT; it++) {
        asm volatile("cp.async.wait_group 1;\n");
        __syncthreads();
        if (it + 2 < NIT) load_stage(it + 2, (it + 2) % NSTAGES);

        const float* As = sm + (it % NSTAGES) * SSTAGE;
        const float* Bs = As + ASTAGE;

        lda_frags(As, 0, af[0]);
        ldb_frags(Bs, 0, bf[0]);

        #pragma unroll
        for (int s = 0; s < 4; s++) {
            int cur = s & 1;
            if (s < 3) {                       // prefetch next kk during HMMAs
                lda_frags(As, (s + 1) * 8, af[cur ^ 1]);
                ldb_frags(Bs, (s + 1) * 8, bf[cur ^ 1]);
            }
            #pragma unroll
            for (int nf = 0; nf < 8; nf++)
                #pragma unroll
                for (int mf = 0; mf < 4; mf++)
                    mma8(acc[mf][nf], af[cur][mf], bf[cur][nf][0], bf[cur][nf][1]);
        }
        __syncthreads();
    }

    // epilogue: bias (+ReLU) (+tf32 round), float2 stores
    #pragma unroll
    for (int mf = 0; mf < 4; mf++) {
        int row0 = am0 + mbase + mf * 16 + g;
        int row1 = row0 + 8;
        #pragma unroll
        for (int nf = 0; nf < 8; nf++) {
            int col = bn0 + nbase + nf * 8 + 2 * t;
            if (col >= N) continue;
            float2 bv = *(const float2*)(bias + col);
            if (row0 < M) {
                float v0 = acc[mf][nf][0] + bv.x;
                float v1 = acc[mf][nf][1] + bv.y;
                if (RELU) { v0 = fmaxf(v0, 0.f); v1 = fmaxf(v1, 0.f); }
                if (ROUND){ v0 = tf32r(v0); v1 = tf32r(v1); }
                *(float2*)(C + (size_t)row0 * N + col) = make_float2(v0, v1);
            }
            if (row1 < M) {
                float v2 = acc[mf][nf][2] + bv.x;
                float v3 = acc[mf][nf][3] + bv.y;
                if (RELU) { v2 = fmaxf(v2, 0.f); v3 = fmaxf(v3, 0.f); }
                if (ROUND){ v2 = tf32r(v2); v3 = tf32r(v3); }
                *(float2*)(C + (size_t)row1 * N + col) = make_float2(v2, v3);
            }
        }
    }
}

// ------------------------- fused GATv2 (R5-proven) -------------------------
__global__ __launch_bounds__(256)
void gat_fused(const float* __restrict__ xl, const float* __restrict__ xr,
               const int* __restrict__ off, const int* __restrict__ csr,
               const int* __restrict__ src, const float* __restrict__ att,
               const float* __restrict__ gat_bias, float* __restrict__ alpha_s,
               float* __restrict__ outm, int N) {
    int n = blockIdx.x;
    if (n >= N) return;
    int t = threadIdx.x;
    int lane = t & 31, wid = t >> 5;
    int b = off[n], e2 = off[n + 1];

    __shared__ float s_xr[4096];
    __shared__ float s_att[4096];
    __shared__ float sm_m[N_HEADS], sm_inv[N_HEADS];

    const float4* xrp = (const float4*)(xr + (size_t)n * 4096);
    const float4* atp = (const float4*)att;
    #pragma unroll
    for (int j = 0; j < 4; j++) {
        int idx = t + j * 256;
        ((float4*)s_xr)[idx]  = xrp[idx];
        ((float4*)s_att)[idx] = atp[idx];
    }
    __syncthreads();

    for (int i = b + wid; i < e2; i += 8) {
        int s = src[csr[i]];
        const float* pl = xl + (size_t)s * 4096;
        float part[N_HEADS];
        #pragma unroll
        for (int h = 0; h < N_HEADS; h++) {
            float p = 0.0f;
            int base = h * 1024;
            #pragma unroll 8
            for (int k = 0; k < 32; k++) {
                int c = base + lane + k * 32;
                float v = pl[c] + s_xr[c];
                v = (v > 0.0f) ? v : NSLOPE * v;
                p += v * s_att[c];
            }
            part[h] = p;
        }
        #pragma unroll
        for (int h = 0; h < N_HEADS; h++) {
            float v = part[h];
            #pragma unroll
            for (int o = 16; o; o >>= 1) v += __shfl_xor_sync(0xffffffffu, v, o);
            if (lane == 0) alpha_s[(size_t)i * N_HEADS + h] = v;
        }
    }
    __syncthreads();

    if (t < N_HEADS) {
        float m = -1e30f;
        for (int i = b; i < e2; i++)
            m = fmaxf(m, alpha_s[(size_t)i * N_HEADS + t]);
        float z = 0.0f;
        for (int i = b; i < e2; i++)
            z += __expf(alpha_s[(size_t)i * N_HEADS + t] - m);
        sm_m[t] = m;
        sm_inv[t] = 1.0f / (z + 1e-16f);
    }
    __syncthreads();
    float mf0 = sm_m[0], mf1 = sm_m[1], mf2 = sm_m[2], mf3 = sm_m[3];
    float iv0 = sm_inv[0], iv1 = sm_inv[1], iv2 = sm_inv[2], iv3 = sm_inv[3];

    float acc[16];
    #pragma unroll
    for (int j = 0; j < 16; j++) acc[j] = 0.0f;

    for (int i = b; i < e2; i++) {
        int s = src[csr[i]];
        const float* pl = xl + (size_t)s * 4096;
        const float* ap = alpha_s + (size_t)i * N_HEADS;
        float w0 = __expf(ap[0] - mf0) * iv0;
        float w1 = __expf(ap[1] - mf1) * iv1;
        float w2 = __expf(ap[2] - mf2) * iv2;
        float w3 = __expf(ap[3] - mf3) * iv3;
        #pragma unroll
        for (int j = 0; j < 4; j++) {
            int c = t + j * 256;
            acc[j]      += w0 * pl[c];
            acc[j + 4]  += w1 * pl[1024 + c];
            acc[j + 8]  += w2 * pl[2048 + c];
            acc[j + 12] += w3 * pl[3072 + c];
        }
    }

    #pragma unroll
    for (int jc = 0; jc < 4; jc++) {
        int c = t + jc * 256;
        float v = 0.25f * (acc[jc] + acc[jc + 4] + acc[jc + 8] + acc[jc + 12]);
        outm[(size_t)n * 1024 + c] = tf32r(v + gat_bias[c]);   // tf32 for final FC
    }
}

// ------------------------- host orchestration -------------------------
static inline dim3 gemm_grid(int M, int N) {
    return dim3((N + BN - 1) / BN, (M + BM - 1) / BM);
}

extern "C" void kernel_launch(void* const* d_in, const int* in_sizes, int n_in,
                              void* d_out, int out_size) {
    const float* x    = (const float*)d_in[0];
    const float* emb  = (const float*)d_in[1];
    const int*   ei   = (const int*)d_in[2];
    const float* exps = (const float*)d_in[3];
    const float* W1   = (const float*)d_in[4];
    const float* b1   = (const float*)d_in[5];
    const float* W2   = (const float*)d_in[6];
    const float* b2   = (const float*)d_in[7];
    const float* Wl   = (const float*)d_in[8];
    const float* bl   = (const float*)d_in[9];
    const float* Wr   = (const float*)d_in[10];
    const float* br   = (const float*)d_in[11];
    const float* att  = (const float*)d_in[12];
    const float* gb   = (const float*)d_in[13];
    const float* Wfc  = (const float*)d_in[14];
    const float* bfc  = (const float*)d_in[15];

    int Nx = in_sizes[0] / 400;
    int Nc = in_sizes[1] / 1024;
    int E  = in_sizes[2] / 2;
    int N  = Nx + Nc;
    int ET = E + N;

    float *xin, *xh, *xc, *xl, *xr, *outm, *alpha, *wbuf;
    int *src, *dst, *deg, *off, *cur, *csr;
    cudaGetSymbolAddress((void**)&xin,   g_xin);
    cudaGetSymbolAddress((void**)&xh,    g_xh);
    cudaGetSymbolAddress((void**)&xc,    g_xc);
    cudaGetSymbolAddress((void**)&xl,    g_xl);
    cudaGetSymbolAddress((void**)&xr,    g_xr);
    cudaGetSymbolAddress((void**)&outm,  g_outm);
    cudaGetSymbolAddress((void**)&alpha, g_alpha);
    cudaGetSymbolAddress((void**)&wbuf,  g_wbuf);
    cudaGetSymbolAddress((void**)&src,   g_src);
    cudaGetSymbolAddress((void**)&dst,   g_dst);
    cudaGetSymbolAddress((void**)&deg,   g_deg);
    cudaGetSymbolAddress((void**)&off,   g_off);
    cudaGetSymbolAddress((void**)&cur,   g_cur);
    cudaGetSymbolAddress((void**)&csr,   g_csr);

    cudaFuncSetAttribute(gemm_tf32<true,  true >, cudaFuncAttributeMaxDynamicSharedMemorySize, GEMM_SMEM_BYTES);
    cudaFuncSetAttribute(gemm_tf32<false, true >, cudaFuncAttributeMaxDynamicSharedMemorySize, GEMM_SMEM_BYTES);
    cudaFuncSetAttribute(gemm_tf32<false, false>, cudaFuncAttributeMaxDynamicSharedMemorySize, GEMM_SMEM_BYTES);

    // 1: round x -> xin
    round_tf32_copy4<<<(Nx * 100 + 255) / 256, 256>>>((const float4*)x, (float4*)xin, Nx * 100);
    // 2: round W1 -> wbuf
    round_tf32_copy4<<<(400 * 128 + 255) / 256, 256>>>((const float4*)W1, (float4*)wbuf, 400 * 128);
    // 3: graph zero (independent filler so slot 4 = GEMM)
    zero_int2<<<(N + 255) / 256, 256>>>(deg, cur, N);
    // 4: MLP-1 (ReLU, rounded output)          [ncu window lands here]
    gemm_tf32<true, true><<<gemm_grid(Nx, 512), 256, GEMM_SMEM_BYTES>>>(xin, wbuf, b1, xh, Nx, 512, 400);
    // 5: round W2
    round_tf32_copy4<<<(512 * 256 + 255) / 256, 256>>>((const float4*)W2, (float4*)wbuf, 512 * 256);
    // 6: MLP-2 (rounded output) -> xc tail
    gemm_tf32<false, true><<<gemm_grid(Nx, 1024), 256, GEMM_SMEM_BYTES>>>(xh, wbuf, b2, xc + (size_t)Nc * 1024, Nx, 1024, 512);
    // 7: centroids (rounded) -> xc head
    round_tf32_copy4<<<(Nc * 256 + 255) / 256, 256>>>((const float4*)emb, (float4*)xc, Nc * 256);
    // 8-9: xl projection
    round_tf32_copy4<<<(1024 * 1024 + 255) / 256, 256>>>((const float4*)Wl, (float4*)wbuf, 1024 * 1024);
    gemm_tf32<false, false><<<gemm_grid(N, 4096), 256, GEMM_SMEM_BYTES>>>(xc, wbuf, bl, xl, N, 4096, 1024);
    // 10-11: xr projection
    round_tf32_copy4<<<(1024 * 1024 + 255) / 256, 256>>>((const float4*)Wr, (float4*)wbuf, 1024 * 1024);
    gemm_tf32<false, false><<<gemm_grid(N, 4096), 256, GEMM_SMEM_BYTES>>>(xc, wbuf, br, xr, N, 4096, 1024);

    // graph structure (deg/cur already zeroed at slot 3)
    build_edges<<<(ET + 255) / 256, 256>>>(ei, src, dst, deg, E, N);
    scan_excl<<<1, 1024>>>(deg, off, N);
    fill_csr<<<(ET + 255) / 256, 256>>>(dst, off, cur, csr, ET);

    // fused GATv2 (writes outm tf32-rounded)
    gat_fused<<<N, 256>>>(xl, xr, off, csr, src, att, gb, alpha, outm, N);

    // final FC
    round_tf32_copy4<<<(1024 * 115 + 255) / 256, 256>>>((const float4*)Wfc, (float4*)wbuf, 1024 * 115);
    gemm_tf32<false, false><<<gemm_grid(N, 460), 256, GEMM_SMEM_BYTES>>>(outm, wbuf, bfc, (float*)d_out, N, 460, 1024);

    // passthrough exps
    copy_f4<<<(Nx * 115 + 255) / 256, 256>>>((const float4*)exps,
                                             (float4*)((float*)d_out + (size_t)N * 460),
                                             Nx * 115);
}

// round 10
// speedup vs baseline: 1.5882x; 1.5882x over previous
#include <cuda_runtime.h>
#include <cuda_fp16.h>
#include <cstdint>

#define N_HEADS 4
#define NSLOPE 0.2f

#define MAXNX 9000
#define MAXNC 1000
#define MAXN  (MAXNX + MAXNC)
#define MAXE0 40000
#define MAXE  (MAXE0 + MAXN)

// ------------------------- static scratch (no allocs) -------------------------
__device__ __half g_hxin[MAXNX * 400];
__device__ __half g_hxh[MAXNX * 512];
__device__ __half g_hxc[MAXN * 1024];
__device__ __half g_hxl[(size_t)MAXN * 4096];
__device__ __half g_hxr[(size_t)MAXN * 4096];
__device__ __half g_houtm[MAXN * 1024];
__device__ __half g_hw[(size_t)4096 * 1024];     // transposed half weights (reused)
__device__ float  g_alpha[MAXE * N_HEADS];
__device__ int    g_src[MAXE];
__device__ int    g_dst[MAXE];
__device__ int    g_deg[MAXN];
__device__ int    g_off[MAXN + 1];
__device__ int    g_cur[MAXN];
__device__ int    g_csr[MAXE];

// ------------------------- helpers -------------------------
__device__ __forceinline__ void cp16(uint32_t saddr, const void* g, bool valid) {
    int sz = valid ? 16 : 0;   // sz=0 -> 16B zero-fill
    asm volatile("cp.async.cg.shared.global [%0], [%1], 16, %2;\n"
                 :: "r"(saddr), "l"(g), "r"(sz));
}

// ------------------------- small utility kernels -------------------------
__global__ void zero_int2(int* a, int* b, int n) {
    int i = blockIdx.x * blockDim.x + threadIdx.x;
    if (i < n) { a[i] = 0; b[i] = 0; }
}
__global__ void copy_f4(const float4* __restrict__ s, float4* __restrict__ d, int n4) {
    int i = blockIdx.x * blockDim.x + threadIdx.x;
    if (i < n4) d[i] = s[i];
}
// float -> half conversion (n must be even; all call sites are)
__global__ void f2h(const float2* __restrict__ a, __half2* __restrict__ b, int n2) {
    int i = blockIdx.x * blockDim.x + threadIdx.x;
    if (i < n2) b[i] = __float22half2_rn(a[i]);
}
// W [K,N] fp32 row-major -> out [N,K] half (K-major rows)
__global__ void transpose_h(const float* __restrict__ in, __half* __restrict__ out,
                            int K, int N) {
    __shared__ float t[32][33];
    int k0 = blockIdx.x * 32, n0 = blockIdx.y * 32;
    int x = threadIdx.x, y = threadIdx.y;
    #pragma unroll
    for (int j = 0; j < 32; j += 8) {
        int k = k0 + y + j, n = n0 + x;
        t[y + j][x] = (k < K && n < N) ? in[(size_t)k * N + n] : 0.0f;
    }
    __syncthreads();
    #pragma unroll
    for (int j = 0; j < 32; j += 8) {
        int n = n0 + y + j, k = k0 + x;
        if (n < N && k < K) out[(size_t)n * K + k] = __float2half(t[x][y + j]);
    }
}

// edge_index is int32 (JAX x64-disabled downcast)
__global__ void build_edges(const int* __restrict__ ei, int* __restrict__ src,
                            int* __restrict__ dst, int* __restrict__ deg, int E, int N) {
    int e = blockIdx.x * blockDim.x + threadIdx.x;
    int ET = E + N;
    if (e >= ET) return;
    int s, d;
    if (e < E) { s = ei[2 * e]; d = ei[2 * e + 1]; }
    else       { s = d = e - E; }
    src[e] = s; dst[e] = d;
    atomicAdd(&deg[d], 1);
}
__global__ void scan_excl(const int* __restrict__ deg, int* __restrict__ off, int n) {
    __shared__ int sh[1024];
    __shared__ int carry;
    if (threadIdx.x == 0) carry = 0;
    __syncthreads();
    for (int base = 0; base < n; base += 1024) {
        int i = base + threadIdx.x;
        int v = (i < n) ? deg[i] : 0;
        sh[threadIdx.x] = v;
        __syncthreads();
        #pragma unroll
        for (int ofs = 1; ofs < 1024; ofs <<= 1) {
            int t = (threadIdx.x >= ofs) ? sh[threadIdx.x - ofs] : 0;
            __syncthreads();
            sh[threadIdx.x] += t;
            __syncthreads();
        }
        if (i < n) off[i] = carry + sh[threadIdx.x] - v;
        __syncthreads();
        if (threadIdx.x == 1023) carry += sh[1023];
        __syncthreads();
    }
    if (threadIdx.x == 0) off[n] = carry;
}
__global__ void fill_csr(const int* __restrict__ dst, const int* __restrict__ off,
                         int* __restrict__ cur, int* __restrict__ csr, int ET) {
    int e = blockIdx.x * blockDim.x + threadIdx.x;
    if (e >= ET) return;
    int d = dst[e];
    int p = off[d] + atomicAdd(&cur[d], 1);
    csr[p] = e;
}

// ===================== fp16 tensor-core GEMM (m16n8k16 + ldmatrix) =====================
// C(MxN) = A(MxK) @ Bt(NxK)^T + bias.  A half row-major [M,K]; Bt half [N,K].
// CTA tile 128x256, BK=32 halves, 8 warps of 64x64, 4-stage cp.async.
// smem rows padded to 40 halves (80B): 16B-group index (5r)%8 -> conflict-free ldmatrix.
#define BM 128
#define BN 256
#define HBK 32
#define HPAD 40
#define HA_HALVES (BM * HPAD)            // 5120
#define HB_HALVES (BN * HPAD)            // 10240
#define HSTG_BYTES ((HA_HALVES + HB_HALVES) * 2)   // 30720
#define HNST 4
#define H_SMEM (HNST * HSTG_BYTES)       // 122880

__device__ __forceinline__ void ldm_x4(uint32_t* d, uint32_t addr) {
    asm volatile("ldmatrix.sync.aligned.m8n8.x4.shared.b16 {%0,%1,%2,%3}, [%4];"
                 : "=r"(d[0]), "=r"(d[1]), "=r"(d[2]), "=r"(d[3]) : "r"(addr));
}
__device__ __forceinline__ void mma16816(float* c, const uint32_t* a, uint32_t b0, uint32_t b1) {
    asm volatile(
        "mma.sync.aligned.m16n8k16.row.col.f32.f16.f16.f32 "
        "{%0,%1,%2,%3}, {%4,%5,%6,%7}, {%8,%9}, {%0,%1,%2,%3};\n"
        : "+f"(c[0]), "+f"(c[1]), "+f"(c[2]), "+f"(c[3])
        : "r"(a[0]), "r"(a[1]), "r"(a[2]), "r"(a[3]), "r"(b0), "r"(b1));
}

template <bool RELU, bool HALF_OUT>
__global__ __launch_bounds__(256)
void gemm_h(const __half* __restrict__ A, const __half* __restrict__ Bt,
            const float* __restrict__ bias, void* __restrict__ Cv,
            int M, int N, int K) {
    extern __shared__ char sm[];
    int tid  = threadIdx.x;
    int warp = tid >> 5;
    int lane = tid & 31;
    int g = lane >> 2;        // 0..7
    int t = lane & 3;         // 0..3
    int wm = warp >> 2;       // 0..1
    int wn = warp & 3;        // 0..3
    int mbase = wm * 64;
    int nbase = wn * 64;
    int am0 = blockIdx.y * BM;
    int bn0 = blockIdx.x * BN;
    int NIT = (K + HBK - 1) / HBK;

    float acc[4][8][4];
    #pragma unroll
    for (int i = 0; i < 4; i++)
        #pragma unroll
        for (int j = 0; j < 8; j++)
            #pragma unroll
            for (int k = 0; k < 4; k++) acc[i][j][k] = 0.0f;

    uint32_t smbase = (uint32_t)__cvta_generic_to_shared(sm);

    auto load_stage = [&](int it, int st) {
        int kt = it * HBK;
        uint32_t ab = smbase + (uint32_t)(st * HSTG_BYTES);
        uint32_t bb = ab + HA_HALVES * 2;
        #pragma unroll
        for (int i = 0; i < 2; i++) {          // A: 512 chunks of 16B
            int idx = tid + i * 256;
            int r = idx >> 2, c = idx & 3;
            int kc = kt + c * 8;
            bool v = (am0 + r < M) && (kc + 8 <= K);
            const __half* gp = A + (size_t)(v ? (am0 + r) : 0) * K + (v ? kc : 0);
            cp16(ab + (uint32_t)(r * 80 + c * 16), gp, v);
        }
        #pragma unroll
        for (int i = 0; i < 4; i++) {          // B: 1024 chunks
            int idx = tid + i * 256;
            int r = idx >> 2, c = idx & 3;
            int kc = kt + c * 8;
            bool v = (bn0 + r < N) && (kc + 8 <= K);
            const __half* gp = Bt + (size_t)(v ? (bn0 + r) : 0) * K + (v ? kc : 0);
            cp16(bb + (uint32_t)(r * 80 + c * 16), gp, v);
        }
        asm volatile("cp.async.commit_group;\n");
    };

    // per-lane ldmatrix address components
    int a_row = lane & 15;                 // rows r0..r0+15
    int a_k   = (lane & 16) >> 1;          // +8 halves for lanes 16-31
    int b_row = (lane & 7) | ((lane & 16) >> 1);   // n rows n0..n0+15
    int b_k   = lane & 8;                  // +8 halves for lanes 8-15 / 24-31

    load_stage(0, 0);
    if (NIT > 1) load_stage(1, 1);
    if (NIT > 2) load_stage(2, 2);

    for (int it = 0; it < NIT; it++) {
        asm volatile("cp.async.wait_group 2;\n");
        __syncthreads();
        if (it + 3 < NIT) load_stage(it + 3, (it + 3) & (HNST - 1));
        else asm volatile("cp.async.commit_group;\n");   // keep 3 groups in flight

        uint32_t ab = smbase + (uint32_t)((it & (HNST - 1)) * HSTG_BYTES);
        uint32_t bb = ab + HA_HALVES * 2;

        #pragma unroll
        for (int kk = 0; kk < HBK; kk += 16) {
            uint32_t a[4][4], b[4][4];
            #pragma unroll
            for (int mf = 0; mf < 4; mf++)
                ldm_x4(a[mf], ab + (uint32_t)((mbase + mf * 16 + a_row) * 80 + (kk + a_k) * 2));
            #pragma unroll
            for (int p = 0; p < 4; p++)
                ldm_x4(b[p], bb + (uint32_t)((nbase + p * 16 + b_row) * 80 + (kk + b_k) * 2));
            #pragma unroll
            for (int p = 0; p < 4; p++)
                #pragma unroll
                for (int mf = 0; mf < 4; mf++) {
                    mma16816(acc[mf][2 * p],     a[mf], b[p][0], b[p][1]);
                    mma16816(acc[mf][2 * p + 1], a[mf], b[p][2], b[p][3]);
                }
        }
        __syncthreads();
    }

    // epilogue
    #pragma unroll
    for (int mf = 0; mf < 4; mf++) {
        int row0 = am0 + mbase + mf * 16 + g;
        int row1 = row0 + 8;
        #pragma unroll
        for (int nf = 0; nf < 8; nf++) {
            int col = bn0 + nbase + nf * 8 + 2 * t;
            if (col >= N) continue;
            float2 bv = *(const float2*)(bias + col);
            float v0 = acc[mf][nf][0] + bv.x;
            float v1 = acc[mf][nf][1] + bv.y;
            float v2 = acc[mf][nf][2] + bv.x;
            float v3 = acc[mf][nf][3] + bv.y;
            if (RELU) {
                v0 = fmaxf(v0, 0.f); v1 = fmaxf(v1, 0.f);
                v2 = fmaxf(v2, 0.f); v3 = fmaxf(v3, 0.f);
            }
            if (HALF_OUT) {
                __half2* C = (__half2*)Cv;
                if (row0 < M) C[((size_t)row0 * N + col) >> 1] = __floats2half2_rn(v0, v1);
                if (row1 < M) C[((size_t)row1 * N + col) >> 1] = __floats2half2_rn(v2, v3);
            } else {
                float* C = (float*)Cv;
                if (row0 < M) *(float2*)(C + (size_t)row0 * N + col) = make_float2(v0, v1);
                if (row1 < M) *(float2*)(C + (size_t)row1 * N + col) = make_float2(v2, v3);
            }
        }
    }
}

// ------------------------- fused GATv2 (half features) -------------------------
__global__ __launch_bounds__(256)
void gat_fused(const __half* __restrict__ xl, const __half* __restrict__ xr,
               const int* __restrict__ off, const int* __restrict__ csr,
               const int* __restrict__ src, const float* __restrict__ att,
               const float* __restrict__ gat_bias, float* __restrict__ alpha_s,
               __half* __restrict__ outm, int N) {
    int n = blockIdx.x;
    if (n >= N) return;
    int t = threadIdx.x;
    int lane = t & 31, wid = t >> 5;
    int b = off[n], e2 = off[n + 1];

    __shared__ float s_xr[4096];
    __shared__ float s_att[4096];
    __shared__ float sm_m[N_HEADS], sm_inv[N_HEADS];

    const __half2* xrp = (const __half2*)(xr + (size_t)n * 4096);
    #pragma unroll
    for (int j = 0; j < 8; j++) {
        int idx = t + j * 256;                 // 2048 half2
        float2 f = __half22float2(xrp[idx]);
        s_xr[2 * idx] = f.x; s_xr[2 * idx + 1] = f.y;
    }
    const float4* atp = (const float4*)att;
    #pragma unroll
    for (int j = 0; j < 4; j++) {
        int idx = t + j * 256;
        ((float4*)s_att)[idx] = atp[idx];
    }
    __syncthreads();

    for (int i = b + wid; i < e2; i += 8) {
        int s = src[csr[i]];
        const __half* pl = xl + (size_t)s * 4096;
        float part[N_HEADS];
        #pragma unroll
        for (int h = 0; h < N_HEADS; h++) {
            float p = 0.0f;
            int base = h * 1024;
            #pragma unroll 8
            for (int k = 0; k < 32; k++) {
                int c = base + lane + k * 32;
                float v = __half2float(pl[c]) + s_xr[c];
                v = (v > 0.0f) ? v : NSLOPE * v;
                p += v * s_att[c];
            }
            part[h] = p;
        }
        #pragma unroll
        for (int h = 0; h < N_HEADS; h++) {
            float v = part[h];
            #pragma unroll
            for (int o = 16; o; o >>= 1) v += __shfl_xor_sync(0xffffffffu, v, o);
            if (lane == 0) alpha_s[(size_t)i * N_HEADS + h] = v;
        }
    }
    __syncthreads();

    if (t < N_HEADS) {
        float m = -1e30f;
        for (int i = b; i < e2; i++)
            m = fmaxf(m, alpha_s[(size_t)i * N_HEADS + t]);
        float z = 0.0f;
        for (int i = b; i < e2; i++)
            z += __expf(alpha_s[(size_t)i * N_HEADS + t] - m);
        sm_m[t] = m;
        sm_inv[t] = 1.0f / (z + 1e-16f);
    }
    __syncthreads();
    float mf0 = sm_m[0], mf1 = sm_m[1], mf2 = sm_m[2], mf3 = sm_m[3];
    float iv0 = sm_inv[0], iv1 = sm_inv[1], iv2 = sm_inv[2], iv3 = sm_inv[3];

    float acc[16];
    #pragma unroll
    for (int j = 0; j < 16; j++) acc[j] = 0.0f;

    for (int i = b; i < e2; i++) {
        int s = src[csr[i]];
        const __half* pl = xl + (size_t)s * 4096;
        const float* ap = alpha_s + (size_t)i * N_HEADS;
        float w0 = __expf(ap[0] - mf0) * iv0;
        float w1 = __expf(ap[1] - mf1) * iv1;
        float w2 = __expf(ap[2] - mf2) * iv2;
        float w3 = __expf(ap[3] - mf3) * iv3;
        #pragma unroll
        for (int j = 0; j < 4; j++) {
            int c = t + j * 256;
            acc[j]      += w0 * __half2float(pl[c]);
            acc[j + 4]  += w1 * __half2float(pl[1024 + c]);
            acc[j + 8]  += w2 * __half2float(pl[2048 + c]);
            acc[j + 12] += w3 * __half2float(pl[3072 + c]);
        }
    }

    #pragma unroll
    for (int jc = 0; jc < 4; jc++) {
        int c = t + jc * 256;
        float v = 0.25f * (acc[jc] + acc[jc + 4] + acc[jc + 8] + acc[jc + 12]);
        outm[(size_t)n * 1024 + c] = __float2half(v + gat_bias[c]);
    }
}

// ------------------------- host orchestration -------------------------
static inline dim3 gemm_grid(int M, int N) {
    return dim3((N + BN - 1) / BN, (M + BM - 1) / BM);
}

extern "C" void kernel_launch(void* const* d_in, const int* in_sizes, int n_in,
                              void* d_out, int out_size) {
    const float* x    = (const float*)d_in[0];
    const float* emb  = (const float*)d_in[1];
    const int*   ei   = (const int*)d_in[2];
    const float* exps = (const float*)d_in[3];
    const float* W1   = (const float*)d_in[4];
    const float* b1   = (const float*)d_in[5];
    const float* W2   = (const float*)d_in[6];
    const float* b2   = (const float*)d_in[7];
    const float* Wl   = (const float*)d_in[8];
    const float* bl   = (const float*)d_in[9];
    const float* Wr   = (const float*)d_in[10];
    const float* br   = (const float*)d_in[11];
    const float* att  = (const float*)d_in[12];
    const float* gb   = (const float*)d_in[13];
    const float* Wfc  = (const float*)d_in[14];
    const float* bfc  = (const float*)d_in[15];

    int Nx = in_sizes[0] / 400;
    int Nc = in_sizes[1] / 1024;
    int E  = in_sizes[2] / 2;
    int N  = Nx + Nc;
    int ET = E + N;

    __half *hxin, *hxh, *hxc, *hxl, *hxr, *houtm, *hw;
    float *alpha;
    int *src, *dst, *deg, *off, *cur, *csr;
    cudaGetSymbolAddress((void**)&hxin,  g_hxin);
    cudaGetSymbolAddress((void**)&hxh,   g_hxh);
    cudaGetSymbolAddress((void**)&hxc,   g_hxc);
    cudaGetSymbolAddress((void**)&hxl,   g_hxl);
    cudaGetSymbolAddress((void**)&hxr,   g_hxr);
    cudaGetSymbolAddress((void**)&houtm, g_houtm);
    cudaGetSymbolAddress((void**)&hw,    g_hw);
    cudaGetSymbolAddress((void**)&alpha, g_alpha);
    cudaGetSymbolAddress((void**)&src,   g_src);
    cudaGetSymbolAddress((void**)&dst,   g_dst);
    cudaGetSymbolAddress((void**)&deg,   g_deg);
    cudaGetSymbolAddress((void**)&off,   g_off);
    cudaGetSymbolAddress((void**)&cur,   g_cur);
    cudaGetSymbolAddress((void**)&csr,   g_csr);

    cudaFuncSetAttribute(gemm_h<true,  true >, cudaFuncAttributeMaxDynamicSharedMemorySize, H_SMEM);
    cudaFuncSetAttribute(gemm_h<false, true >, cudaFuncAttributeMaxDynamicSharedMemorySize, H_SMEM);
    cudaFuncSetAttribute(gemm_h<false, false>, cudaFuncAttributeMaxDynamicSharedMemorySize, H_SMEM);

    dim3 tb(32, 8);

    // 1: x -> half
    f2h<<<(Nx * 200 + 255) / 256, 256>>>((const float2*)x, (__half2*)hxin, Nx * 200);
    // 2: W1^T -> half [512,400]
    transpose_h<<<dim3(13, 16), tb>>>(W1, hw, 400, 512);
    // 3: graph zero (filler so slot 4 is a GEMM)
    zero_int2<<<(N + 255) / 256, 256>>>(deg, cur, N);
    // 4: MLP-1 (ReLU, half out)
    gemm_h<true, true><<<gemm_grid(Nx, 512), 256, H_SMEM>>>(hxin, hw, b1, hxh, Nx, 512, 400);
    // 5: W2^T [1024,512]
    transpose_h<<<dim3(16, 32), tb>>>(W2, hw, 512, 1024);
    // 6: MLP-2 -> xc tail (half)
    gemm_h<false, true><<<gemm_grid(Nx, 1024), 256, H_SMEM>>>(hxh, hw, b2, hxc + (size_t)Nc * 1024, Nx, 1024, 512);
    // 7: centroids -> xc head (half)
    f2h<<<(Nc * 512 + 255) / 256, 256>>>((const float2*)emb, (__half2*)hxc, Nc * 512);
    // 8-9: xl projection
    transpose_h<<<dim3(32, 128), tb>>>(Wl, hw, 1024, 4096);
    gemm_h<false, true><<<gemm_grid(N, 4096), 256, H_SMEM>>>(hxc, hw, bl, hxl, N, 4096, 1024);
    // 10-11: xr projection
    transpose_h<<<dim3(32, 128), tb>>>(Wr, hw, 1024, 4096);
    gemm_h<false, true><<<gemm_grid(N, 4096), 256, H_SMEM>>>(hxc, hw, br, hxr, N, 4096, 1024);

    // graph structure (deg/cur zeroed at slot 3)
    build_edges<<<(ET + 255) / 256, 256>>>(ei, src, dst, deg, E, N);
    scan_excl<<<1, 1024>>>(deg, off, N);
    fill_csr<<<(ET + 255) / 256, 256>>>(dst, off, cur, csr, ET);

    // fused GATv2 (half in, half out)
    gat_fused<<<N, 256>>>(hxl, hxr, off, csr, src, att, gb, alpha, houtm, N);

    // final FC (float out into d_out)
    transpose_h<<<dim3(32, 15), tb>>>(Wfc, hw, 1024, 460);
    gemm_h<false, false><<<gemm_grid(N, 460), 256, H_SMEM>>>(houtm, hw, bfc, (float*)d_out, N, 460, 1024);

    // passthrough exps
    copy_f4<<<(Nx * 115 + 255) / 256, 256>>>((const float4*)exps,
                                             (float4*)((float*)d_out + (size_t)N * 460),
                                             Nx * 115);
}

// round 11
// speedup vs baseline: 1.8236x; 1.1483x over previous
#include <cuda_runtime.h>
#include <cuda_fp16.h>
#include <cstdint>

#define N_HEADS 4
#define NSLOPE 0.2f

#define MAXNX 9000
#define MAXNC 1000
#define MAXN  (MAXNX + MAXNC)
#define MAXE0 40000
#define MAXE  (MAXE0 + MAXN)

// ------------------------- static scratch (no allocs) -------------------------
__device__ __half g_hxin[MAXNX * 400];
__device__ __half g_hxh[MAXNX * 512];
__device__ __half g_hxc[MAXN * 1024];
__device__ __half g_hxl[(size_t)MAXN * 4096];
__device__ __half g_hxr[(size_t)MAXN * 4096];
__device__ __half g_houtm[MAXN * 1024];
__device__ __half g_hw[(size_t)4096 * 1024];     // transposed half weights (reused)
__device__ float  g_alpha[MAXE * N_HEADS];
__device__ int    g_src[MAXE];
__device__ int    g_dst[MAXE];
__device__ int    g_deg[MAXN];
__device__ int    g_off[MAXN + 1];
__device__ int    g_cur[MAXN];
__device__ int    g_csr[MAXE];

// ------------------------- helpers -------------------------
__device__ __forceinline__ void cp16(uint32_t saddr, const void* g, bool valid) {
    int sz = valid ? 16 : 0;   // sz=0 -> 16B zero-fill
    asm volatile("cp.async.cg.shared.global [%0], [%1], 16, %2;\n"
                 :: "r"(saddr), "l"(g), "r"(sz));
}

// ------------------------- small utility kernels -------------------------
__global__ void zero_int2(int* a, int* b, int n) {
    int i = blockIdx.x * blockDim.x + threadIdx.x;
    if (i < n) { a[i] = 0; b[i] = 0; }
}
__global__ void copy_f4(const float4* __restrict__ s, float4* __restrict__ d, int n4) {
    int i = blockIdx.x * blockDim.x + threadIdx.x;
    if (i < n4) d[i] = s[i];
}
__global__ void f2h(const float2* __restrict__ a, __half2* __restrict__ b, int n2) {
    int i = blockIdx.x * blockDim.x + threadIdx.x;
    if (i < n2) b[i] = __float22half2_rn(a[i]);
}
// W [K,N] fp32 row-major -> out [N,K] half (K-major rows)
__global__ void transpose_h(const float* __restrict__ in, __half* __restrict__ out,
                            int K, int N) {
    __shared__ float t[32][33];
    int k0 = blockIdx.x * 32, n0 = blockIdx.y * 32;
    int x = threadIdx.x, y = threadIdx.y;
    #pragma unroll
    for (int j = 0; j < 32; j += 8) {
        int k = k0 + y + j, n = n0 + x;
        t[y + j][x] = (k < K && n < N) ? in[(size_t)k * N + n] : 0.0f;
    }
    __syncthreads();
    #pragma unroll
    for (int j = 0; j < 32; j += 8) {
        int n = n0 + y + j, k = k0 + x;
        if (n < N && k < K) out[(size_t)n * K + k] = __float2half(t[x][y + j]);
    }
}

// edge_index is int32 (JAX x64-disabled downcast)
__global__ void build_edges(const int* __restrict__ ei, int* __restrict__ src,
                            int* __restrict__ dst, int* __restrict__ deg, int E, int N) {
    int e = blockIdx.x * blockDim.x + threadIdx.x;
    int ET = E + N;
    if (e >= ET) return;
    int s, d;
    if (e < E) { s = ei[2 * e]; d = ei[2 * e + 1]; }
    else       { s = d = e - E; }
    src[e] = s; dst[e] = d;
    atomicAdd(&deg[d], 1);
}
__global__ void scan_excl(const int* __restrict__ deg, int* __restrict__ off, int n) {
    __shared__ int sh[1024];
    __shared__ int carry;
    if (threadIdx.x == 0) carry = 0;
    __syncthreads();
    for (int base = 0; base < n; base += 1024) {
        int i = base + threadIdx.x;
        int v = (i < n) ? deg[i] : 0;
        sh[threadIdx.x] = v;
        __syncthreads();
        #pragma unroll
        for (int ofs = 1; ofs < 1024; ofs <<= 1) {
            int t = (threadIdx.x >= ofs) ? sh[threadIdx.x - ofs] : 0;
            __syncthreads();
            sh[threadIdx.x] += t;
            __syncthreads();
        }
        if (i < n) off[i] = carry + sh[threadIdx.x] - v;
        __syncthreads();
        if (threadIdx.x == 1023) carry += sh[1023];
        __syncthreads();
    }
    if (threadIdx.x == 0) off[n] = carry;
}
__global__ void fill_csr(const int* __restrict__ dst, const int* __restrict__ off,
                         int* __restrict__ cur, int* __restrict__ csr, int ET) {
    int e = blockIdx.x * blockDim.x + threadIdx.x;
    if (e >= ET) return;
    int d = dst[e];
    int p = off[d] + atomicAdd(&cur[d], 1);
    csr[p] = e;
}

// ===================== fp16 tensor-core GEMM (m16n8k16 + ldmatrix) =====================
// C(MxN) = A(MxK) @ Bt(NxK)^T + bias.  A half row-major [M,K]; Bt half [N,K].
// CTA tile 128x128, BK=32 halves, 8 warps of 64x32, 4-stage cp.async.
// 80KB smem + <=128 regs -> 2 CTAs/SM (cross-CTA latency hiding).
// smem rows padded to 40 halves (80B): 16B-group (5r)%8 -> conflict-free ldmatrix.
#define BM 128
#define BN 128
#define HBK 32
#define HPAD 40
#define HA_HALVES (BM * HPAD)            // 5120
#define HB_HALVES (BN * HPAD)            // 5120
#define HSTG_BYTES ((HA_HALVES + HB_HALVES) * 2)   // 20480
#define HNST 4
#define H_SMEM (HNST * HSTG_BYTES)       // 81920 -> 2 CTAs/SM

__device__ __forceinline__ void ldm_x4(uint32_t* d, uint32_t addr) {
    asm volatile("ldmatrix.sync.aligned.m8n8.x4.shared.b16 {%0,%1,%2,%3}, [%4];"
                 : "=r"(d[0]), "=r"(d[1]), "=r"(d[2]), "=r"(d[3]) : "r"(addr));
}
__device__ __forceinline__ void mma16816(float* c, const uint32_t* a, uint32_t b0, uint32_t b1) {
    asm volatile(
        "mma.sync.aligned.m16n8k16.row.col.f32.f16.f16.f32 "
        "{%0,%1,%2,%3}, {%4,%5,%6,%7}, {%8,%9}, {%0,%1,%2,%3};\n"
        : "+f"(c[0]), "+f"(c[1]), "+f"(c[2]), "+f"(c[3])
        : "r"(a[0]), "r"(a[1]), "r"(a[2]), "r"(a[3]), "r"(b0), "r"(b1));
}

template <bool RELU, bool HALF_OUT>
__global__ __launch_bounds__(256, 2)
void gemm_h(const __half* __restrict__ A, const __half* __restrict__ Bt,
            const float* __restrict__ bias, void* __restrict__ Cv,
            int M, int N, int K) {
    extern __shared__ char sm[];
    int tid  = threadIdx.x;
    int warp = tid >> 5;
    int lane = tid & 31;
    int g = lane >> 2;        // 0..7
    int t = lane & 3;         // 0..3
    int wm = warp >> 2;       // 0..1
    int wn = warp & 3;        // 0..3
    int mbase = wm * 64;
    int nbase = wn * 32;
    int am0 = blockIdx.y * BM;
    int bn0 = blockIdx.x * BN;
    int NIT = (K + HBK - 1) / HBK;

    float acc[4][4][4];
    #pragma unroll
    for (int i = 0; i < 4; i++)
        #pragma unroll
        for (int j = 0; j < 4; j++)
            #pragma unroll
            for (int k = 0; k < 4; k++) acc[i][j][k] = 0.0f;

    uint32_t smbase = (uint32_t)__cvta_generic_to_shared(sm);

    auto load_stage = [&](int it, int st) {
        int kt = it * HBK;
        uint32_t ab = smbase + (uint32_t)(st * HSTG_BYTES);
        uint32_t bb = ab + HA_HALVES * 2;
        #pragma unroll
        for (int i = 0; i < 2; i++) {          // A: 512 chunks of 16B
            int idx = tid + i * 256;
            int r = idx >> 2, c = idx & 3;
            int kc = kt + c * 8;
            bool v = (am0 + r < M) && (kc + 8 <= K);
            const __half* gp = A + (size_t)(v ? (am0 + r) : 0) * K + (v ? kc : 0);
            cp16(ab + (uint32_t)(r * 80 + c * 16), gp, v);
        }
        #pragma unroll
        for (int i = 0; i < 2; i++) {          // B: 512 chunks
            int idx = tid + i * 256;
            int r = idx >> 2, c = idx & 3;
            int kc = kt + c * 8;
            bool v = (bn0 + r < N) && (kc + 8 <= K);
            const __half* gp = Bt + (size_t)(v ? (bn0 + r) : 0) * K + (v ? kc : 0);
            cp16(bb + (uint32_t)(r * 80 + c * 16), gp, v);
        }
        asm volatile("cp.async.commit_group;\n");
    };

    // per-lane ldmatrix address components
    int a_row = lane & 15;
    int a_k   = (lane & 16) >> 1;
    int b_row = (lane & 7) | ((lane & 16) >> 1);
    int b_k   = lane & 8;

    load_stage(0, 0);
    if (NIT > 1) load_stage(1, 1);
    if (NIT > 2) load_stage(2, 2);

    for (int it = 0; it < NIT; it++) {
        asm volatile("cp.async.wait_group 2;\n");
        __syncthreads();
        if (it + 3 < NIT) load_stage(it + 3, (it + 3) & (HNST - 1));
        else asm volatile("cp.async.commit_group;\n");

        uint32_t ab = smbase + (uint32_t)((it & (HNST - 1)) * HSTG_BYTES);
        uint32_t bb = ab + HA_HALVES * 2;

        #pragma unroll
        for (int kk = 0; kk < HBK; kk += 16) {
            uint32_t a[4][4], b[2][4];
            #pragma unroll
            for (int mf = 0; mf < 4; mf++)
                ldm_x4(a[mf], ab + (uint32_t)((mbase + mf * 16 + a_row) * 80 + (kk + a_k) * 2));
            #pragma unroll
            for (int p = 0; p < 2; p++)
                ldm_x4(b[p], bb + (uint32_t)((nbase + p * 16 + b_row) * 80 + (kk + b_k) * 2));
            #pragma unroll
            for (int p = 0; p < 2; p++)
                #pragma unroll
                for (int mf = 0; mf < 4; mf++) {
                    mma16816(acc[mf][2 * p],     a[mf], b[p][0], b[p][1]);
                    mma16816(acc[mf][2 * p + 1], a[mf], b[p][2], b[p][3]);
                }
        }
        __syncthreads();
    }

    // epilogue
    #pragma unroll
    for (int mf = 0; mf < 4; mf++) {
        int row0 = am0 + mbase + mf * 16 + g;
        int row1 = row0 + 8;
        #pragma unroll
        for (int nf = 0; nf < 4; nf++) {
            int col = bn0 + nbase + nf * 8 + 2 * t;
            if (col >= N) continue;
            float2 bv = *(const float2*)(bias + col);
            float v0 = acc[mf][nf][0] + bv.x;
            float v1 = acc[mf][nf][1] + bv.y;
            float v2 = acc[mf][nf][2] + bv.x;
            float v3 = acc[mf][nf][3] + bv.y;
            if (RELU) {
                v0 = fmaxf(v0, 0.f); v1 = fmaxf(v1, 0.f);
                v2 = fmaxf(v2, 0.f); v3 = fmaxf(v3, 0.f);
            }
            if (HALF_OUT) {
                __half2* C = (__half2*)Cv;
                if (row0 < M) C[((size_t)row0 * N + col) >> 1] = __floats2half2_rn(v0, v1);
                if (row1 < M) C[((size_t)row1 * N + col) >> 1] = __floats2half2_rn(v2, v3);
            } else {
                float* C = (float*)Cv;
                if (row0 < M) *(float2*)(C + (size_t)row0 * N + col) = make_float2(v0, v1);
                if (row1 < M) *(float2*)(C + (size_t)row1 * N + col) = make_float2(v2, v3);
            }
        }
    }
}

// ------------------------- fused GATv2 (half features) -------------------------
__global__ __launch_bounds__(256)
void gat_fused(const __half* __restrict__ xl, const __half* __restrict__ xr,
               const int* __restrict__ off, const int* __restrict__ csr,
               const int* __restrict__ src, const float* __restrict__ att,
               const float* __restrict__ gat_bias, float* __restrict__ alpha_s,
               __half* __restrict__ outm, int N) {
    int n = blockIdx.x;
    if (n >= N) return;
    int t = threadIdx.x;
    int lane = t & 31, wid = t >> 5;
    int b = off[n], e2 = off[n + 1];

    __shared__ float s_xr[4096];
    __shared__ float s_att[4096];
    __shared__ float sm_m[N_HEADS], sm_inv[N_HEADS];

    const __half2* xrp = (const __half2*)(xr + (size_t)n * 4096);
    #pragma unroll
    for (int j = 0; j < 8; j++) {
        int idx = t + j * 256;
        float2 f = __half22float2(xrp[idx]);
        s_xr[2 * idx] = f.x; s_xr[2 * idx + 1] = f.y;
    }
    const float4* atp = (const float4*)att;
    #pragma unroll
    for (int j = 0; j < 4; j++) {
        int idx = t + j * 256;
        ((float4*)s_att)[idx] = atp[idx];
    }
    __syncthreads();

    for (int i = b + wid; i < e2; i += 8) {
        int s = src[csr[i]];
        const __half* pl = xl + (size_t)s * 4096;
        float part[N_HEADS];
        #pragma unroll
        for (int h = 0; h < N_HEADS; h++) {
            float p = 0.0f;
            int base = h * 1024;
            #pragma unroll 8
            for (int k = 0; k < 32; k++) {
                int c = base + lane + k * 32;
                float v = __half2float(pl[c]) + s_xr[c];
                v = (v > 0.0f) ? v : NSLOPE * v;
                p += v * s_att[c];
            }
            part[h] = p;
        }
        #pragma unroll
        for (int h = 0; h < N_HEADS; h++) {
            float v = part[h];
            #pragma unroll
            for (int o = 16; o; o >>= 1) v += __shfl_xor_sync(0xffffffffu, v, o);
            if (lane == 0) alpha_s[(size_t)i * N_HEADS + h] = v;
        }
    }
    __syncthreads();

    if (t < N_HEADS) {
        float m = -1e30f;
        for (int i = b; i < e2; i++)
            m = fmaxf(m, alpha_s[(size_t)i * N_HEADS + t]);
        float z = 0.0f;
        for (int i = b; i < e2; i++)
            z += __expf(alpha_s[(size_t)i * N_HEADS + t] - m);
        sm_m[t] = m;
        sm_inv[t] = 1.0f / (z + 1e-16f);
    }
    __syncthreads();
    float mf0 = sm_m[0], mf1 = sm_m[1], mf2 = sm_m[2], mf3 = sm_m[3];
    float iv0 = sm_inv[0], iv1 = sm_inv[1], iv2 = sm_inv[2], iv3 = sm_inv[3];

    float acc[16];
    #pragma unroll
    for (int j = 0; j < 16; j++) acc[j] = 0.0f;

    for (int i = b; i < e2; i++) {
        int s = src[csr[i]];
        const __half* pl = xl + (size_t)s * 4096;
        const float* ap = alpha_s + (size_t)i * N_HEADS;
        float w0 = __expf(ap[0] - mf0) * iv0;
        float w1 = __expf(ap[1] - mf1) * iv1;
        float w2 = __expf(ap[2] - mf2) * iv2;
        float w3 = __expf(ap[3] - mf3) * iv3;
        #pragma unroll
        for (int j = 0; j < 4; j++) {
            int c = t + j * 256;
            acc[j]      += w0 * __half2float(pl[c]);
            acc[j + 4]  += w1 * __half2float(pl[1024 + c]);
            acc[j + 8]  += w2 * __half2float(pl[2048 + c]);
            acc[j + 12] += w3 * __half2float(pl[3072 + c]);
        }
    }

    #pragma unroll
    for (int jc = 0; jc < 4; jc++) {
        int c = t + jc * 256;
        float v = 0.25f * (acc[jc] + acc[jc + 4] + acc[jc + 8] + acc[jc + 12]);
        outm[(size_t)n * 1024 + c] = __float2half(v + gat_bias[c]);
    }
}

// ------------------------- host orchestration -------------------------
static inline dim3 gemm_grid(int M, int N) {
    return dim3((N + BN - 1) / BN, (M + BM - 1) / BM);
}

extern "C" void kernel_launch(void* const* d_in, const int* in_sizes, int n_in,
                              void* d_out, int out_size) {
    const float* x    = (const float*)d_in[0];
    const float* emb  = (const float*)d_in[1];
    const int*   ei   = (const int*)d_in[2];
    const float* exps = (const float*)d_in[3];
    const float* W1   = (const float*)d_in[4];
    const float* b1   = (const float*)d_in[5];
    const float* W2   = (const float*)d_in[6];
    const float* b2   = (const float*)d_in[7];
    const float* Wl   = (const float*)d_in[8];
    const float* bl   = (const float*)d_in[9];
    const float* Wr   = (const float*)d_in[10];
    const float* br   = (const float*)d_in[11];
    const float* att  = (const float*)d_in[12];
    const float* gb   = (const float*)d_in[13];
    const float* Wfc  = (const float*)d_in[14];
    const float* bfc  = (const float*)d_in[15];

    int Nx = in_sizes[0] / 400;
    int Nc = in_sizes[1] / 1024;
    int E  = in_sizes[2] / 2;
    int N  = Nx + Nc;
    int ET = E + N;

    __half *hxin, *hxh, *hxc, *hxl, *hxr, *houtm, *hw;
    float *alpha;
    int *src, *dst, *deg, *off, *cur, *csr;
    cudaGetSymbolAddress((void**)&hxin,  g_hxin);
    cudaGetSymbolAddress((void**)&hxh,   g_hxh);
    cudaGetSymbolAddress((void**)&hxc,   g_hxc);
    cudaGetSymbolAddress((void**)&hxl,   g_hxl);
    cudaGetSymbolAddress((void**)&hxr,   g_hxr);
    cudaGetSymbolAddress((void**)&houtm, g_houtm);
    cudaGetSymbolAddress((void**)&hw,    g_hw);
    cudaGetSymbolAddress((void**)&alpha, g_alpha);
    cudaGetSymbolAddress((void**)&src,   g_src);
    cudaGetSymbolAddress((void**)&dst,   g_dst);
    cudaGetSymbolAddress((void**)&deg,   g_deg);
    cudaGetSymbolAddress((void**)&off,   g_off);
    cudaGetSymbolAddress((void**)&cur,   g_cur);
    cudaGetSymbolAddress((void**)&csr,   g_csr);

    cudaFuncSetAttribute(gemm_h<true,  true >, cudaFuncAttributeMaxDynamicSharedMemorySize, H_SMEM);
    cudaFuncSetAttribute(gemm_h<false, true >, cudaFuncAttributeMaxDynamicSharedMemorySize, H_SMEM);
    cudaFuncSetAttribute(gemm_h<false, false>, cudaFuncAttributeMaxDynamicSharedMemorySize, H_SMEM);

    dim3 tb(32, 8);

    // 1: x -> half
    f2h<<<(Nx * 200 + 255) / 256, 256>>>((const float2*)x, (__half2*)hxin, Nx * 200);
    // 2: W1^T -> half [512,400]
    transpose_h<<<dim3(13, 16), tb>>>(W1, hw, 400, 512);
    // 3: graph zero (filler so slot 4 is a GEMM)
    zero_int2<<<(N + 255) / 256, 256>>>(deg, cur, N);
    // 4: MLP-1 (ReLU, half out)                       [ncu window]
    gemm_h<true, true><<<gemm_grid(Nx, 512), 256, H_SMEM>>>(hxin, hw, b1, hxh, Nx, 512, 400);
    // 5: W2^T [1024,512]
    transpose_h<<<dim3(16, 32), tb>>>(W2, hw, 512, 1024);
    // 6: MLP-2 -> xc tail (half)
    gemm_h<false, true><<<gemm_grid(Nx, 1024), 256, H_SMEM>>>(hxh, hw, b2, hxc + (size_t)Nc * 1024, Nx, 1024, 512);
    // 7: centroids -> xc head (half)
    f2h<<<(Nc * 512 + 255) / 256, 256>>>((const float2*)emb, (__half2*)hxc, Nc * 512);
    // 8-9: xl projection
    transpose_h<<<dim3(32, 128), tb>>>(Wl, hw, 1024, 4096);
    gemm_h<false, true><<<gemm_grid(N, 4096), 256, H_SMEM>>>(hxc, hw, bl, hxl, N, 4096, 1024);
    // 10-11: xr projection
    transpose_h<<<dim3(32, 128), tb>>>(Wr, hw, 1024, 4096);
    gemm_h<false, true><<<gemm_grid(N, 4096), 256, H_SMEM>>>(hxc, hw, br, hxr, N, 4096, 1024);

    // graph structure (deg/cur zeroed at slot 3)
    build_edges<<<(ET + 255) / 256, 256>>>(ei, src, dst, deg, E, N);
    scan_excl<<<1, 1024>>>(deg, off, N);
    fill_csr<<<(ET + 255) / 256, 256>>>(dst, off, cur, csr, ET);

    // fused GATv2 (half in, half out)
    gat_fused<<<N, 256>>>(hxl, hxr, off, csr, src, att, gb, alpha, houtm, N);

    // final FC (float out into d_out)
    transpose_h<<<dim3(32, 15), tb>>>(Wfc, hw, 1024, 460);
    gemm_h<false, false><<<gemm_grid(N, 460), 256, H_SMEM>>>(houtm, hw, bfc, (float*)d_out, N, 460, 1024);

    // passthrough exps
    copy_f4<<<(Nx * 115 + 255) / 256, 256>>>((const float4*)exps,
                                             (float4*)((float*)d_out + (size_t)N * 460),
                                             Nx * 115);
}

// round 12
// speedup vs baseline: 1.9195x; 1.0525x over previous
#include <cuda_runtime.h>
#include <cuda_fp16.h>
#include <cstdint>

#define N_HEADS 4
#define NSLOPE 0.2f

#define MAXNX 9000
#define MAXNC 1000
#define MAXN  (MAXNX + MAXNC)
#define MAXE0 40000
#define MAXE  (MAXE0 + MAXN)

// ------------------------- static scratch (no allocs) -------------------------
__device__ __half g_hxin[MAXNX * 400];
__device__ __half g_hxh[MAXNX * 512];
__device__ __half g_hxc[MAXN * 1024];
__device__ __half g_hxl[(size_t)MAXN * 4096];
__device__ __half g_hxr[(size_t)MAXN * 4096];
__device__ __half g_houtm[MAXN * 1024];
__device__ __half g_hw[(size_t)4096 * 1024];     // transposed half weights (reused)
__device__ float  g_alpha[MAXE * N_HEADS];
__device__ int    g_src[MAXE];
__device__ int    g_dst[MAXE];
__device__ int    g_deg[MAXN];
__device__ int    g_off[MAXN + 1];
__device__ int    g_cur[MAXN];
__device__ int    g_csr[MAXE];

// ------------------------- helpers -------------------------
__device__ __forceinline__ void cp16(uint32_t saddr, const void* g, bool valid) {
    int sz = valid ? 16 : 0;   // sz=0 -> 16B zero-fill
    asm volatile("cp.async.cg.shared.global [%0], [%1], 16, %2;\n"
                 :: "r"(saddr), "l"(g), "r"(sz));
}

// ------------------------- small utility kernels -------------------------
__global__ void zero_int2(int* a, int* b, int n) {
    int i = blockIdx.x * blockDim.x + threadIdx.x;
    if (i < n) { a[i] = 0; b[i] = 0; }
}
__global__ void copy_f4(const float4* __restrict__ s, float4* __restrict__ d, int n4) {
    int i = blockIdx.x * blockDim.x + threadIdx.x;
    if (i < n4) d[i] = s[i];
}
__global__ void f2h(const float2* __restrict__ a, __half2* __restrict__ b, int n2) {
    int i = blockIdx.x * blockDim.x + threadIdx.x;
    if (i < n2) b[i] = __float22half2_rn(a[i]);
}
// W [K,N] fp32 row-major -> out [N,K] half (K-major rows)
__global__ void transpose_h(const float* __restrict__ in, __half* __restrict__ out,
                            int K, int N) {
    __shared__ float t[32][33];
    int k0 = blockIdx.x * 32, n0 = blockIdx.y * 32;
    int x = threadIdx.x, y = threadIdx.y;
    #pragma unroll
    for (int j = 0; j < 32; j += 8) {
        int k = k0 + y + j, n = n0 + x;
        t[y + j][x] = (k < K && n < N) ? in[(size_t)k * N + n] : 0.0f;
    }
    __syncthreads();
    #pragma unroll
    for (int j = 0; j < 32; j += 8) {
        int n = n0 + y + j, k = k0 + x;
        if (n < N && k < K) out[(size_t)n * K + k] = __float2half(t[x][y + j]);
    }
}

// edge_index is int32 (JAX x64-disabled downcast)
__global__ void build_edges(const int* __restrict__ ei, int* __restrict__ src,
                            int* __restrict__ dst, int* __restrict__ deg, int E, int N) {
    int e = blockIdx.x * blockDim.x + threadIdx.x;
    int ET = E + N;
    if (e >= ET) return;
    int s, d;
    if (e < E) { s = ei[2 * e]; d = ei[2 * e + 1]; }
    else       { s = d = e - E; }
    src[e] = s; dst[e] = d;
    atomicAdd(&deg[d], 1);
}
__global__ void scan_excl(const int* __restrict__ deg, int* __restrict__ off, int n) {
    __shared__ int sh[1024];
    __shared__ int carry;
    if (threadIdx.x == 0) carry = 0;
    __syncthreads();
    for (int base = 0; base < n; base += 1024) {
        int i = base + threadIdx.x;
        int v = (i < n) ? deg[i] : 0;
        sh[threadIdx.x] = v;
        __syncthreads();
        #pragma unroll
        for (int ofs = 1; ofs < 1024; ofs <<= 1) {
            int t = (threadIdx.x >= ofs) ? sh[threadIdx.x - ofs] : 0;
            __syncthreads();
            sh[threadIdx.x] += t;
            __syncthreads();
        }
        if (i < n) off[i] = carry + sh[threadIdx.x] - v;
        __syncthreads();
        if (threadIdx.x == 1023) carry += sh[1023];
        __syncthreads();
    }
    if (threadIdx.x == 0) off[n] = carry;
}
__global__ void fill_csr(const int* __restrict__ dst, const int* __restrict__ off,
                         int* __restrict__ cur, int* __restrict__ csr, int ET) {
    int e = blockIdx.x * blockDim.x + threadIdx.x;
    if (e >= ET) return;
    int d = dst[e];
    int p = off[d] + atomicAdd(&cur[d], 1);
    csr[p] = e;
}

// ===================== fp16 tensor-core GEMM (m16n8k16 + ldmatrix) =====================
// C(MxN) = A(MxK) @ Bt(NxK)^T + bias.  A half row-major [M,K]; Bt half [N,K].
// CTA tile 128x128, BK=64 halves, 8 warps of 64x32, 3-stage cp.async.
// 108KB smem + <=128 regs -> 2 CTAs/SM; 16 barrier points per K=1024 (was 32).
// smem rows padded to 72 halves (144B = 9 x 16B groups): group (r+c)%8 -> conflict-free.
#define BM 128
#define BN 128
#define HBK 64
#define HPAD 72
#define HA_HALVES (BM * HPAD)            // 9216
#define HB_HALVES (BN * HPAD)            // 9216
#define HSTG_BYTES ((HA_HALVES + HB_HALVES) * 2)   // 36864
#define HNST 3
#define H_SMEM (HNST * HSTG_BYTES)       // 110592 -> 2 CTAs/SM

__device__ __forceinline__ void ldm_x4(uint32_t* d, uint32_t addr) {
    asm volatile("ldmatrix.sync.aligned.m8n8.x4.shared.b16 {%0,%1,%2,%3}, [%4];"
                 : "=r"(d[0]), "=r"(d[1]), "=r"(d[2]), "=r"(d[3]) : "r"(addr));
}
__device__ __forceinline__ void mma16816(float* c, const uint32_t* a, uint32_t b0, uint32_t b1) {
    asm volatile(
        "mma.sync.aligned.m16n8k16.row.col.f32.f16.f16.f32 "
        "{%0,%1,%2,%3}, {%4,%5,%6,%7}, {%8,%9}, {%0,%1,%2,%3};\n"
        : "+f"(c[0]), "+f"(c[1]), "+f"(c[2]), "+f"(c[3])
        : "r"(a[0]), "r"(a[1]), "r"(a[2]), "r"(a[3]), "r"(b0), "r"(b1));
}

template <bool RELU, bool HALF_OUT>
__global__ __launch_bounds__(256, 2)
void gemm_h(const __half* __restrict__ A, const __half* __restrict__ Bt,
            const float* __restrict__ bias, void* __restrict__ Cv,
            int M, int N, int K) {
    extern __shared__ char sm[];
    int tid  = threadIdx.x;
    int warp = tid >> 5;
    int lane = tid & 31;
    int g = lane >> 2;        // 0..7
    int t = lane & 3;         // 0..3
    int wm = warp >> 2;       // 0..1
    int wn = warp & 3;        // 0..3
    int mbase = wm * 64;
    int nbase = wn * 32;
    int am0 = blockIdx.y * BM;
    int bn0 = blockIdx.x * BN;
    int NIT = (K + HBK - 1) / HBK;

    float acc[4][4][4];
    #pragma unroll
    for (int i = 0; i < 4; i++)
        #pragma unroll
        for (int j = 0; j < 4; j++)
            #pragma unroll
            for (int k = 0; k < 4; k++) acc[i][j][k] = 0.0f;

    uint32_t smbase = (uint32_t)__cvta_generic_to_shared(sm);

    auto load_stage = [&](int it, int st) {
        int kt = it * HBK;
        uint32_t ab = smbase + (uint32_t)(st * HSTG_BYTES);
        uint32_t bb = ab + HA_HALVES * 2;
        #pragma unroll
        for (int i = 0; i < 4; i++) {          // A: 128 rows x 8 chunks of 16B
            int idx = tid + i * 256;
            int r = idx >> 3, c = idx & 7;
            int kc = kt + c * 8;
            bool v = (am0 + r < M) && (kc + 8 <= K);
            const __half* gp = A + (size_t)(v ? (am0 + r) : 0) * K + (v ? kc : 0);
            cp16(ab + (uint32_t)(r * 144 + c * 16), gp, v);
        }
        #pragma unroll
        for (int i = 0; i < 4; i++) {          // B: 128 rows x 8 chunks
            int idx = tid + i * 256;
            int r = idx >> 3, c = idx & 7;
            int kc = kt + c * 8;
            bool v = (bn0 + r < N) && (kc + 8 <= K);
            const __half* gp = Bt + (size_t)(v ? (bn0 + r) : 0) * K + (v ? kc : 0);
            cp16(bb + (uint32_t)(r * 144 + c * 16), gp, v);
        }
        asm volatile("cp.async.commit_group;\n");
    };

    // per-lane ldmatrix address components
    int a_row = lane & 15;
    int a_k   = (lane & 16) >> 1;
    int b_row = (lane & 7) | ((lane & 16) >> 1);
    int b_k   = lane & 8;

    load_stage(0, 0);
    if (NIT > 1) load_stage(1, 1);

    for (int it = 0; it < NIT; it++) {
        asm volatile("cp.async.wait_group 1;\n");
        __syncthreads();
        if (it + 2 < NIT) load_stage(it + 2, (it + 2) % HNST);

        uint32_t ab = smbase + (uint32_t)((it % HNST) * HSTG_BYTES);
        uint32_t bb = ab + HA_HALVES * 2;

        #pragma unroll
        for (int kk = 0; kk < HBK; kk += 16) {
            uint32_t a[4][4], b[2][4];
            #pragma unroll
            for (int mf = 0; mf < 4; mf++)
                ldm_x4(a[mf], ab + (uint32_t)((mbase + mf * 16 + a_row) * 144 + (kk + a_k) * 2));
            #pragma unroll
            for (int p = 0; p < 2; p++)
                ldm_x4(b[p], bb + (uint32_t)((nbase + p * 16 + b_row) * 144 + (kk + b_k) * 2));
            #pragma unroll
            for (int p = 0; p < 2; p++)
                #pragma unroll
                for (int mf = 0; mf < 4; mf++) {
                    mma16816(acc[mf][2 * p],     a[mf], b[p][0], b[p][1]);
                    mma16816(acc[mf][2 * p + 1], a[mf], b[p][2], b[p][3]);
                }
        }
        __syncthreads();
    }

    // epilogue
    #pragma unroll
    for (int mf = 0; mf < 4; mf++) {
        int row0 = am0 + mbase + mf * 16 + g;
        int row1 = row0 + 8;
        #pragma unroll
        for (int nf = 0; nf < 4; nf++) {
            int col = bn0 + nbase + nf * 8 + 2 * t;
            if (col >= N) continue;
            float2 bv = *(const float2*)(bias + col);
            float v0 = acc[mf][nf][0] + bv.x;
            float v1 = acc[mf][nf][1] + bv.y;
            float v2 = acc[mf][nf][2] + bv.x;
            float v3 = acc[mf][nf][3] + bv.y;
            if (RELU) {
                v0 = fmaxf(v0, 0.f); v1 = fmaxf(v1, 0.f);
                v2 = fmaxf(v2, 0.f); v3 = fmaxf(v3, 0.f);
            }
            if (HALF_OUT) {
                __half2* C = (__half2*)Cv;
                if (row0 < M) C[((size_t)row0 * N + col) >> 1] = __floats2half2_rn(v0, v1);
                if (row1 < M) C[((size_t)row1 * N + col) >> 1] = __floats2half2_rn(v2, v3);
            } else {
                float* C = (float*)Cv;
                if (row0 < M) *(float2*)(C + (size_t)row0 * N + col) = make_float2(v0, v1);
                if (row1 < M) *(float2*)(C + (size_t)row1 * N + col) = make_float2(v2, v3);
            }
        }
    }
}

// ------------------------- fused GATv2 (half features) -------------------------
__global__ __launch_bounds__(256)
void gat_fused(const __half* __restrict__ xl, const __half* __restrict__ xr,
               const int* __restrict__ off, const int* __restrict__ csr,
               const int* __restrict__ src, const float* __restrict__ att,
               const float* __restrict__ gat_bias, float* __restrict__ alpha_s,
               __half* __restrict__ outm, int N) {
    int n = blockIdx.x;
    if (n >= N) return;
    int t = threadIdx.x;
    int lane = t & 31, wid = t >> 5;
    int b = off[n], e2 = off[n + 1];

    __shared__ float s_xr[4096];
    __shared__ float s_att[4096];
    __shared__ float sm_m[N_HEADS], sm_inv[N_HEADS];

    const __half2* xrp = (const __half2*)(xr + (size_t)n * 4096);
    #pragma unroll
    for (int j = 0; j < 8; j++) {
        int idx = t + j * 256;
        float2 f = __half22float2(xrp[idx]);
        s_xr[2 * idx] = f.x; s_xr[2 * idx + 1] = f.y;
    }
    const float4* atp = (const float4*)att;
    #pragma unroll
    for (int j = 0; j < 4; j++) {
        int idx = t + j * 256;
        ((float4*)s_att)[idx] = atp[idx];
    }
    __syncthreads();

    for (int i = b + wid; i < e2; i += 8) {
        int s = src[csr[i]];
        const __half* pl = xl + (size_t)s * 4096;
        float part[N_HEADS];
        #pragma unroll
        for (int h = 0; h < N_HEADS; h++) {
            float p = 0.0f;
            int base = h * 1024;
            #pragma unroll 8
            for (int k = 0; k < 32; k++) {
                int c = base + lane + k * 32;
                float v = __half2float(pl[c]) + s_xr[c];
                v = (v > 0.0f) ? v : NSLOPE * v;
                p += v * s_att[c];
            }
            part[h] = p;
        }
        #pragma unroll
        for (int h = 0; h < N_HEADS; h++) {
            float v = part[h];
            #pragma unroll
            for (int o = 16; o; o >>= 1) v += __shfl_xor_sync(0xffffffffu, v, o);
            if (lane == 0) alpha_s[(size_t)i * N_HEADS + h] = v;
        }
    }
    __syncthreads();

    if (t < N_HEADS) {
        float m = -1e30f;
        for (int i = b; i < e2; i++)
            m = fmaxf(m, alpha_s[(size_t)i * N_HEADS + t]);
        float z = 0.0f;
        for (int i = b; i < e2; i++)
            z += __expf(alpha_s[(size_t)i * N_HEADS + t] - m);
        sm_m[t] = m;
        sm_inv[t] = 1.0f / (z + 1e-16f);
    }
    __syncthreads();
    float mf0 = sm_m[0], mf1 = sm_m[1], mf2 = sm_m[2], mf3 = sm_m[3];
    float iv0 = sm_inv[0], iv1 = sm_inv[1], iv2 = sm_inv[2], iv3 = sm_inv[3];

    float acc[16];
    #pragma unroll
    for (int j = 0; j < 16; j++) acc[j] = 0.0f;

    for (int i = b; i < e2; i++) {
        int s = src[csr[i]];
        const __half* pl = xl + (size_t)s * 4096;
        const float* ap = alpha_s + (size_t)i * N_HEADS;
        float w0 = __expf(ap[0] - mf0) * iv0;
        float w1 = __expf(ap[1] - mf1) * iv1;
        float w2 = __expf(ap[2] - mf2) * iv2;
        float w3 = __expf(ap[3] - mf3) * iv3;
        #pragma unroll
        for (int j = 0; j < 4; j++) {
            int c = t + j * 256;
            acc[j]      += w0 * __half2float(pl[c]);
            acc[j + 4]  += w1 * __half2float(pl[1024 + c]);
            acc[j + 8]  += w2 * __half2float(pl[2048 + c]);
            acc[j + 12] += w3 * __half2float(pl[3072 + c]);
        }
    }

    #pragma unroll
    for (int jc = 0; jc < 4; jc++) {
        int c = t + jc * 256;
        float v = 0.25f * (acc[jc] + acc[jc + 4] + acc[jc + 8] + acc[jc + 12]);
        outm[(size_t)n * 1024 + c] = __float2half(v + gat_bias[c]);
    }
}

// ------------------------- host orchestration -------------------------
static inline dim3 gemm_grid(int M, int N) {
    return dim3((N + BN - 1) / BN, (M + BM - 1) / BM);
}

extern "C" void kernel_launch(void* const* d_in, const int* in_sizes, int n_in,
                              void* d_out, int out_size) {
    const float* x    = (const float*)d_in[0];
    const float* emb  = (const float*)d_in[1];
    const int*   ei   = (const int*)d_in[2];
    const float* exps = (const float*)d_in[3];
    const float* W1   = (const float*)d_in[4];
    const float* b1   = (const float*)d_in[5];
    const float* W2   = (const float*)d_in[6];
    const float* b2   = (const float*)d_in[7];
    const float* Wl   = (const float*)d_in[8];
    const float* bl   = (const float*)d_in[9];
    const float* Wr   = (const float*)d_in[10];
    const float* br   = (const float*)d_in[11];
    const float* att  = (const float*)d_in[12];
    const float* gb   = (const float*)d_in[13];
    const float* Wfc  = (const float*)d_in[14];
    const float* bfc  = (const float*)d_in[15];

    int Nx = in_sizes[0] / 400;
    int Nc = in_sizes[1] / 1024;
    int E  = in_sizes[2] / 2;
    int N  = Nx + Nc;
    int ET = E + N;

    __half *hxin, *hxh, *hxc, *hxl, *hxr, *houtm, *hw;
    float *alpha;
    int *src, *dst, *deg, *off, *cur, *csr;
    cudaGetSymbolAddress((void**)&hxin,  g_hxin);
    cudaGetSymbolAddress((void**)&hxh,   g_hxh);
    cudaGetSymbolAddress((void**)&hxc,   g_hxc);
    cudaGetSymbolAddress((void**)&hxl,   g_hxl);
    cudaGetSymbolAddress((void**)&hxr,   g_hxr);
    cudaGetSymbolAddress((void**)&houtm, g_houtm);
    cudaGetSymbolAddress((void**)&hw,    g_hw);
    cudaGetSymbolAddress((void**)&alpha, g_alpha);
    cudaGetSymbolAddress((void**)&src,   g_src);
    cudaGetSymbolAddress((void**)&dst,   g_dst);
    cudaGetSymbolAddress((void**)&deg,   g_deg);
    cudaGetSymbolAddress((void**)&off,   g_off);
    cudaGetSymbolAddress((void**)&cur,   g_cur);
    cudaGetSymbolAddress((void**)&csr,   g_csr);

    cudaFuncSetAttribute(gemm_h<true,  true >, cudaFuncAttributeMaxDynamicSharedMemorySize, H_SMEM);
    cudaFuncSetAttribute(gemm_h<false, true >, cudaFuncAttributeMaxDynamicSharedMemorySize, H_SMEM);
    cudaFuncSetAttribute(gemm_h<false, false>, cudaFuncAttributeMaxDynamicSharedMemorySize, H_SMEM);

    dim3 tb(32, 8);

    // 1: x -> half
    f2h<<<(Nx * 200 + 255) / 256, 256>>>((const float2*)x, (__half2*)hxin, Nx * 200);
    // 2: W1^T -> half [512,400]
    transpose_h<<<dim3(13, 16), tb>>>(W1, hw, 400, 512);
    // 3: graph zero (filler so slot 4 is a GEMM)
    zero_int2<<<(N + 255) / 256, 256>>>(deg, cur, N);
    // 4: MLP-1 (ReLU, half out)                       [ncu window]
    gemm_h<true, true><<<gemm_grid(Nx, 512), 256, H_SMEM>>>(hxin, hw, b1, hxh, Nx, 512, 400);
    // 5: W2^T [1024,512]
    transpose_h<<<dim3(16, 32), tb>>>(W2, hw, 512, 1024);
    // 6: MLP-2 -> xc tail (half)
    gemm_h<false, true><<<gemm_grid(Nx, 1024), 256, H_SMEM>>>(hxh, hw, b2, hxc + (size_t)Nc * 1024, Nx, 1024, 512);
    // 7: centroids -> xc head (half)
    f2h<<<(Nc * 512 + 255) / 256, 256>>>((const float2*)emb, (__half2*)hxc, Nc * 512);
    // 8-9: xl projection
    transpose_h<<<dim3(32, 128), tb>>>(Wl, hw, 1024, 4096);
    gemm_h<false, true><<<gemm_grid(N, 4096), 256, H_SMEM>>>(hxc, hw, bl, hxl, N, 4096, 1024);
    // 10-11: xr projection
    transpose_h<<<dim3(32, 128), tb>>>(Wr, hw, 1024, 4096);
    gemm_h<false, true><<<gemm_grid(N, 4096), 256, H_SMEM>>>(hxc, hw, br, hxr, N, 4096, 1024);

    // graph structure (deg/cur zeroed at slot 3)
    build_edges<<<(ET + 255) / 256, 256>>>(ei, src, dst, deg, E, N);
    scan_excl<<<1, 1024>>>(deg, off, N);
    fill_csr<<<(ET + 255) / 256, 256>>>(dst, off, cur, csr, ET);

    // fused GATv2 (half in, half out)
    gat_fused<<<N, 256>>>(hxl, hxr, off, csr, src, att, gb, alpha, houtm, N);

    // final FC (float out into d_out)
    transpose_h<<<dim3(32, 15), tb>>>(Wfc, hw, 1024, 460);
    gemm_h<false, false><<<gemm_grid(N, 460), 256, H_SMEM>>>(houtm, hw, bfc, (float*)d_out, N, 460, 1024);

    // passthrough exps
    copy_f4<<<(Nx * 115 + 255) / 256, 256>>>((const float4*)exps,
                                             (float4*)((float*)d_out + (size_t)N * 460),
                                             Nx * 115);
}

// round 13
// speedup vs baseline: 1.9953x; 1.0395x over previous
#include <cuda_runtime.h>
#include <cuda_fp16.h>
#include <cstdint>

#define N_HEADS 4
#define NSLOPE 0.2f

#define MAXNX 9000
#define MAXNC 1000
#define MAXN  (MAXNX + MAXNC)
#define MAXE0 40000
#define MAXE  (MAXE0 + MAXN)

// ------------------------- static scratch (no allocs) -------------------------
__device__ __half g_hxin[MAXNX * 400];
__device__ __half g_hxh[MAXNX * 512];
__device__ __half g_hxc[MAXN * 1024];
__device__ __half g_hxlr[(size_t)MAXN * 8192];   // [n, 0:4096)=xl, [4096:8192)=xr
__device__ __half g_houtm[MAXN * 1024];
__device__ __half g_hw1[512 * 400];
__device__ __half g_hw2[1024 * 512];
__device__ __half g_hwlr[(size_t)8192 * 1024];   // Wl^T rows 0-4095, Wr^T rows 4096-8191
__device__ __half g_hwfc[460 * 1024];
__device__ float  g_bcat[8192];
__device__ float  g_alpha[MAXE * N_HEADS];
__device__ int    g_src[MAXE];
__device__ int    g_dst[MAXE];
__device__ int    g_deg[MAXN];
__device__ int    g_off[MAXN + 1];
__device__ int    g_cur[MAXN];
__device__ int    g_csr[MAXE];

// ------------------------- helpers -------------------------
__device__ __forceinline__ void cp16(uint32_t saddr, const void* g, bool valid) {
    int sz = valid ? 16 : 0;   // sz=0 -> 16B zero-fill
    asm volatile("cp.async.cg.shared.global [%0], [%1], 16, %2;\n"
                 :: "r"(saddr), "l"(g), "r"(sz));
}

// ------------------------- small utility kernels -------------------------
__global__ void zero_int2(int* a, int* b, int n) {
    int i = blockIdx.x * blockDim.x + threadIdx.x;
    if (i < n) { a[i] = 0; b[i] = 0; }
}
__global__ void copy_f4(const float4* __restrict__ s, float4* __restrict__ d, int n4) {
    int i = blockIdx.x * blockDim.x + threadIdx.x;
    if (i < n4) d[i] = s[i];
}
__global__ void f2h(const float2* __restrict__ a, __half2* __restrict__ b, int n2) {
    int i = blockIdx.x * blockDim.x + threadIdx.x;
    if (i < n2) b[i] = __float22half2_rn(a[i]);
}
// W [K,N] fp32 row-major -> out [N,K] half (K-major rows)
__global__ void transpose_h(const float* __restrict__ in, __half* __restrict__ out,
                            int K, int N) {
    __shared__ float t[32][33];
    int k0 = blockIdx.x * 32, n0 = blockIdx.y * 32;
    int x = threadIdx.x, y = threadIdx.y;
    #pragma unroll
    for (int j = 0; j < 32; j += 8) {
        int k = k0 + y + j, n = n0 + x;
        t[y + j][x] = (k < K && n < N) ? in[(size_t)k * N + n] : 0.0f;
    }
    __syncthreads();
    #pragma unroll
    for (int j = 0; j < 32; j += 8) {
        int n = n0 + y + j, k = k0 + x;
        if (n < N && k < K) out[(size_t)n * K + k] = __float2half(t[x][y + j]);
    }
}

// edge_index is int32 (JAX x64-disabled downcast)
__global__ void build_edges(const int* __restrict__ ei, int* __restrict__ src,
                            int* __restrict__ dst, int* __restrict__ deg, int E, int N) {
    int e = blockIdx.x * blockDim.x + threadIdx.x;
    int ET = E + N;
    if (e >= ET) return;
    int s, d;
    if (e < E) { s = ei[2 * e]; d = ei[2 * e + 1]; }
    else       { s = d = e - E; }
    src[e] = s; dst[e] = d;
    atomicAdd(&deg[d], 1);
}
__global__ void scan_excl(const int* __restrict__ deg, int* __restrict__ off, int n) {
    __shared__ int sh[1024];
    __shared__ int carry;
    if (threadIdx.x == 0) carry = 0;
    __syncthreads();
    for (int base = 0; base < n; base += 1024) {
        int i = base + threadIdx.x;
        int v = (i < n) ? deg[i] : 0;
        sh[threadIdx.x] = v;
        __syncthreads();
        #pragma unroll
        for (int ofs = 1; ofs < 1024; ofs <<= 1) {
            int t = (threadIdx.x >= ofs) ? sh[threadIdx.x - ofs] : 0;
            __syncthreads();
            sh[threadIdx.x] += t;
            __syncthreads();
        }
        if (i < n) off[i] = carry + sh[threadIdx.x] - v;
        __syncthreads();
        if (threadIdx.x == 1023) carry += sh[1023];
        __syncthreads();
    }
    if (threadIdx.x == 0) off[n] = carry;
}
__global__ void fill_csr(const int* __restrict__ dst, const int* __restrict__ off,
                         int* __restrict__ cur, int* __restrict__ csr, int ET) {
    int e = blockIdx.x * blockDim.x + threadIdx.x;
    if (e >= ET) return;
    int d = dst[e];
    int p = off[d] + atomicAdd(&cur[d], 1);
    csr[p] = e;
}

// ===================== fp16 tensor-core GEMM (m16n8k16 + ldmatrix) =====================
// C(MxN) = A(MxK) @ Bt(NxK)^T + bias.  CTA 128x128, BK=64, 8 warps of 64x32,
// 3-stage cp.async, 110KB smem + <=128 regs -> 2 CTAs/SM.
// smem rows padded to 72 halves (144B = 9 x 16B groups): group (r+c)%8 conflict-free.
#define BM 128
#define BN 128
#define HBK 64
#define HPAD 72
#define HA_HALVES (BM * HPAD)
#define HB_HALVES (BN * HPAD)
#define HSTG_BYTES ((HA_HALVES + HB_HALVES) * 2)
#define HNST 3
#define H_SMEM (HNST * HSTG_BYTES)

__device__ __forceinline__ void ldm_x4(uint32_t* d, uint32_t addr) {
    asm volatile("ldmatrix.sync.aligned.m8n8.x4.shared.b16 {%0,%1,%2,%3}, [%4];"
                 : "=r"(d[0]), "=r"(d[1]), "=r"(d[2]), "=r"(d[3]) : "r"(addr));
}
__device__ __forceinline__ void mma16816(float* c, const uint32_t* a, uint32_t b0, uint32_t b1) {
    asm volatile(
        "mma.sync.aligned.m16n8k16.row.col.f32.f16.f16.f32 "
        "{%0,%1,%2,%3}, {%4,%5,%6,%7}, {%8,%9}, {%0,%1,%2,%3};\n"
        : "+f"(c[0]), "+f"(c[1]), "+f"(c[2]), "+f"(c[3])
        : "r"(a[0]), "r"(a[1]), "r"(a[2]), "r"(a[3]), "r"(b0), "r"(b1));
}

template <bool RELU, bool HALF_OUT>
__global__ __launch_bounds__(256, 2)
void gemm_h(const __half* __restrict__ A, const __half* __restrict__ Bt,
            const float* __restrict__ bias, void* __restrict__ Cv,
            int M, int N, int K) {
    extern __shared__ char sm[];
    int tid  = threadIdx.x;
    int warp = tid >> 5;
    int lane = tid & 31;
    int g = lane >> 2;
    int t = lane & 3;
    int wm = warp >> 2;
    int wn = warp & 3;
    int mbase = wm * 64;
    int nbase = wn * 32;
    int am0 = blockIdx.y * BM;
    int bn0 = blockIdx.x * BN;
    int NIT = (K + HBK - 1) / HBK;

    float acc[4][4][4];
    #pragma unroll
    for (int i = 0; i < 4; i++)
        #pragma unroll
        for (int j = 0; j < 4; j++)
            #pragma unroll
            for (int k = 0; k < 4; k++) acc[i][j][k] = 0.0f;

    uint32_t smbase = (uint32_t)__cvta_generic_to_shared(sm);

    auto load_stage = [&](int it, int st) {
        int kt = it * HBK;
        uint32_t ab = smbase + (uint32_t)(st * HSTG_BYTES);
        uint32_t bb = ab + HA_HALVES * 2;
        #pragma unroll
        for (int i = 0; i < 4; i++) {
            int idx = tid + i * 256;
            int r = idx >> 3, c = idx & 7;
            int kc = kt + c * 8;
            bool v = (am0 + r < M) && (kc + 8 <= K);
            const __half* gp = A + (size_t)(v ? (am0 + r) : 0) * K + (v ? kc : 0);
            cp16(ab + (uint32_t)(r * 144 + c * 16), gp, v);
        }
        #pragma unroll
        for (int i = 0; i < 4; i++) {
            int idx = tid + i * 256;
            int r = idx >> 3, c = idx & 7;
            int kc = kt + c * 8;
            bool v = (bn0 + r < N) && (kc + 8 <= K);
            const __half* gp = Bt + (size_t)(v ? (bn0 + r) : 0) * K + (v ? kc : 0);
            cp16(bb + (uint32_t)(r * 144 + c * 16), gp, v);
        }
        asm volatile("cp.async.commit_group;\n");
    };

    int a_row = lane & 15;
    int a_k   = (lane & 16) >> 1;
    int b_row = (lane & 7) | ((lane & 16) >> 1);
    int b_k   = lane & 8;

    load_stage(0, 0);
    if (NIT > 1) load_stage(1, 1);

    for (int it = 0; it < NIT; it++) {
        asm volatile("cp.async.wait_group 1;\n");
        __syncthreads();
        if (it + 2 < NIT) load_stage(it + 2, (it + 2) % HNST);

        uint32_t ab = smbase + (uint32_t)((it % HNST) * HSTG_BYTES);
        uint32_t bb = ab + HA_HALVES * 2;

        #pragma unroll
        for (int kk = 0; kk < HBK; kk += 16) {
            uint32_t a[4][4], b[2][4];
            #pragma unroll
            for (int mf = 0; mf < 4; mf++)
                ldm_x4(a[mf], ab + (uint32_t)((mbase + mf * 16 + a_row) * 144 + (kk + a_k) * 2));
            #pragma unroll
            for (int p = 0; p < 2; p++)
                ldm_x4(b[p], bb + (uint32_t)((nbase + p * 16 + b_row) * 144 + (kk + b_k) * 2));
            #pragma unroll
            for (int p = 0; p < 2; p++)
                #pragma unroll
                for (int mf = 0; mf < 4; mf++) {
                    mma16816(acc[mf][2 * p],     a[mf], b[p][0], b[p][1]);
                    mma16816(acc[mf][2 * p + 1], a[mf], b[p][2], b[p][3]);
                }
        }
        __syncthreads();
    }

    #pragma unroll
    for (int mf = 0; mf < 4; mf++) {
        int row0 = am0 + mbase + mf * 16 + g;
        int row1 = row0 + 8;
        #pragma unroll
        for (int nf = 0; nf < 4; nf++) {
            int col = bn0 + nbase + nf * 8 + 2 * t;
            if (col >= N) continue;
            float2 bv = *(const float2*)(bias + col);
            float v0 = acc[mf][nf][0] + bv.x;
            float v1 = acc[mf][nf][1] + bv.y;
            float v2 = acc[mf][nf][2] + bv.x;
            float v3 = acc[mf][nf][3] + bv.y;
            if (RELU) {
                v0 = fmaxf(v0, 0.f); v1 = fmaxf(v1, 0.f);
                v2 = fmaxf(v2, 0.f); v3 = fmaxf(v3, 0.f);
            }
            if (HALF_OUT) {
                __half2* C = (__half2*)Cv;
                if (row0 < M) C[((size_t)row0 * N + col) >> 1] = __floats2half2_rn(v0, v1);
                if (row1 < M) C[((size_t)row1 * N + col) >> 1] = __floats2half2_rn(v2, v3);
            } else {
                float* C = (float*)Cv;
                if (row0 < M) *(float2*)(C + (size_t)row0 * N + col) = make_float2(v0, v1);
                if (row1 < M) *(float2*)(C + (size_t)row1 * N + col) = make_float2(v2, v3);
            }
        }
    }
}

// ------------------------- fused GATv2 (xlr rows: [xl | xr], stride 8192) ------
__global__ __launch_bounds__(256)
void gat_fused(const __half* __restrict__ xlr,
               const int* __restrict__ off, const int* __restrict__ csr,
               const int* __restrict__ src, const float* __restrict__ att,
               const float* __restrict__ gat_bias, float* __restrict__ alpha_s,
               __half* __restrict__ outm, int N) {
    int n = blockIdx.x;
    if (n >= N) return;
    int t = threadIdx.x;
    int lane = t & 31, wid = t >> 5;
    int b = off[n], e2 = off[n + 1];

    __shared__ float s_xr[4096];
    __shared__ float s_att[4096];
    __shared__ float sm_m[N_HEADS], sm_inv[N_HEADS];

    const __half2* xrp = (const __half2*)(xlr + (size_t)n * 8192 + 4096);
    #pragma unroll
    for (int j = 0; j < 8; j++) {
        int idx = t + j * 256;
        float2 f = __half22float2(xrp[idx]);
        s_xr[2 * idx] = f.x; s_xr[2 * idx + 1] = f.y;
    }
    const float4* atp = (const float4*)att;
    #pragma unroll
    for (int j = 0; j < 4; j++) {
        int idx = t + j * 256;
        ((float4*)s_att)[idx] = atp[idx];
    }
    __syncthreads();

    for (int i = b + wid; i < e2; i += 8) {
        int s = src[csr[i]];
        const __half* pl = xlr + (size_t)s * 8192;
        float part[N_HEADS];
        #pragma unroll
        for (int h = 0; h < N_HEADS; h++) {
            float p = 0.0f;
            int base = h * 1024;
            #pragma unroll 8
            for (int k = 0; k < 32; k++) {
                int c = base + lane + k * 32;
                float v = __half2float(pl[c]) + s_xr[c];
                v = (v > 0.0f) ? v : NSLOPE * v;
                p += v * s_att[c];
            }
            part[h] = p;
        }
        #pragma unroll
        for (int h = 0; h < N_HEADS; h++) {
            float v = part[h];
            #pragma unroll
            for (int o = 16; o; o >>= 1) v += __shfl_xor_sync(0xffffffffu, v, o);
            if (lane == 0) alpha_s[(size_t)i * N_HEADS + h] = v;
        }
    }
    __syncthreads();

    if (t < N_HEADS) {
        float m = -1e30f;
        for (int i = b; i < e2; i++)
            m = fmaxf(m, alpha_s[(size_t)i * N_HEADS + t]);
        float z = 0.0f;
        for (int i = b; i < e2; i++)
            z += __expf(alpha_s[(size_t)i * N_HEADS + t] - m);
        sm_m[t] = m;
        sm_inv[t] = 1.0f / (z + 1e-16f);
    }
    __syncthreads();
    float mf0 = sm_m[0], mf1 = sm_m[1], mf2 = sm_m[2], mf3 = sm_m[3];
    float iv0 = sm_inv[0], iv1 = sm_inv[1], iv2 = sm_inv[2], iv3 = sm_inv[3];

    float acc[16];
    #pragma unroll
    for (int j = 0; j < 16; j++) acc[j] = 0.0f;

    for (int i = b; i < e2; i++) {
        int s = src[csr[i]];
        const __half* pl = xlr + (size_t)s * 8192;
        const float* ap = alpha_s + (size_t)i * N_HEADS;
        float w0 = __expf(ap[0] - mf0) * iv0;
        float w1 = __expf(ap[1] - mf1) * iv1;
        float w2 = __expf(ap[2] - mf2) * iv2;
        float w3 = __expf(ap[3] - mf3) * iv3;
        #pragma unroll
        for (int j = 0; j < 4; j++) {
            int c = t + j * 256;
            acc[j]      += w0 * __half2float(pl[c]);
            acc[j + 4]  += w1 * __half2float(pl[1024 + c]);
            acc[j + 8]  += w2 * __half2float(pl[2048 + c]);
            acc[j + 12] += w3 * __half2float(pl[3072 + c]);
        }
    }

    #pragma unroll
    for (int jc = 0; jc < 4; jc++) {
        int c = t + jc * 256;
        float v = 0.25f * (acc[jc] + acc[jc + 4] + acc[jc + 8] + acc[jc + 12]);
        outm[(size_t)n * 1024 + c] = __float2half(v + gat_bias[c]);
    }
}

// ------------------------- host orchestration -------------------------
static inline dim3 gemm_grid(int M, int N) {
    return dim3((N + BN - 1) / BN, (M + BM - 1) / BM);
}

extern "C" void kernel_launch(void* const* d_in, const int* in_sizes, int n_in,
                              void* d_out, int out_size) {
    const float* x    = (const float*)d_in[0];
    const float* emb  = (const float*)d_in[1];
    const int*   ei   = (const int*)d_in[2];
    const float* exps = (const float*)d_in[3];
    const float* W1   = (const float*)d_in[4];
    const float* b1   = (const float*)d_in[5];
    const float* W2   = (const float*)d_in[6];
    const float* b2   = (const float*)d_in[7];
    const float* Wl   = (const float*)d_in[8];
    const float* bl   = (const float*)d_in[9];
    const float* Wr   = (const float*)d_in[10];
    const float* br   = (const float*)d_in[11];
    const float* att  = (const float*)d_in[12];
    const float* gb   = (const float*)d_in[13];
    const float* Wfc  = (const float*)d_in[14];
    const float* bfc  = (const float*)d_in[15];

    int Nx = in_sizes[0] / 400;
    int Nc = in_sizes[1] / 1024;
    int E  = in_sizes[2] / 2;
    int N  = Nx + Nc;
    int ET = E + N;

    __half *hxin, *hxh, *hxc, *hxlr, *houtm, *hw1, *hw2, *hwlr, *hwfc;
    float *alpha, *bcat;
    int *src, *dst, *deg, *off, *cur, *csr;
    cudaGetSymbolAddress((void**)&hxin,  g_hxin);
    cudaGetSymbolAddress((void**)&hxh,   g_hxh);
    cudaGetSymbolAddress((void**)&hxc,   g_hxc);
    cudaGetSymbolAddress((void**)&hxlr,  g_hxlr);
    cudaGetSymbolAddress((void**)&houtm, g_houtm);
    cudaGetSymbolAddress((void**)&hw1,   g_hw1);
    cudaGetSymbolAddress((void**)&hw2,   g_hw2);
    cudaGetSymbolAddress((void**)&hwlr,  g_hwlr);
    cudaGetSymbolAddress((void**)&hwfc,  g_hwfc);
    cudaGetSymbolAddress((void**)&bcat,  g_bcat);
    cudaGetSymbolAddress((void**)&alpha, g_alpha);
    cudaGetSymbolAddress((void**)&src,   g_src);
    cudaGetSymbolAddress((void**)&dst,   g_dst);
    cudaGetSymbolAddress((void**)&deg,   g_deg);
    cudaGetSymbolAddress((void**)&off,   g_off);
    cudaGetSymbolAddress((void**)&cur,   g_cur);
    cudaGetSymbolAddress((void**)&csr,   g_csr);

    cudaFuncSetAttribute(gemm_h<true,  true >, cudaFuncAttributeMaxDynamicSharedMemorySize, H_SMEM);
    cudaFuncSetAttribute(gemm_h<false, true >, cudaFuncAttributeMaxDynamicSharedMemorySize, H_SMEM);
    cudaFuncSetAttribute(gemm_h<false, false>, cudaFuncAttributeMaxDynamicSharedMemorySize, H_SMEM);

    dim3 tb(32, 8);
    cudaStream_t s0 = 0, s1, s2;
    cudaStreamCreate(&s1);
    cudaStreamCreate(&s2);
    cudaEvent_t eFork, eW1, eW2, eWlr, eWfc, eGraph;
    cudaEventCreateWithFlags(&eFork, cudaEventDisableTiming);
    cudaEventCreateWithFlags(&eW1,   cudaEventDisableTiming);
    cudaEventCreateWithFlags(&eW2,   cudaEventDisableTiming);
    cudaEventCreateWithFlags(&eWlr,  cudaEventDisableTiming);
    cudaEventCreateWithFlags(&eWfc,  cudaEventDisableTiming);
    cudaEventCreateWithFlags(&eGraph,cudaEventDisableTiming);

    // ---- fork side streams ----
    cudaEventRecord(eFork, s0);
    cudaStreamWaitEvent(s1, eFork, 0);
    cudaStreamWaitEvent(s2, eFork, 0);

    // ---- s1: weight prep (overlaps main-chain GEMMs) ----
    transpose_h<<<dim3(13, 16), tb, 0, s1>>>(W1, hw1, 400, 512);
    cudaEventRecord(eW1, s1);
    transpose_h<<<dim3(16, 32), tb, 0, s1>>>(W2, hw2, 512, 1024);
    cudaEventRecord(eW2, s1);
    transpose_h<<<dim3(32, 128), tb, 0, s1>>>(Wl, hwlr, 1024, 4096);
    transpose_h<<<dim3(32, 128), tb, 0, s1>>>(Wr, hwlr + (size_t)4096 * 1024, 1024, 4096);
    copy_f4<<<4, 256, 0, s1>>>((const float4*)bl, (float4*)bcat, 1024);
    copy_f4<<<4, 256, 0, s1>>>((const float4*)br, (float4*)(bcat + 4096), 1024);
    cudaEventRecord(eWlr, s1);
    transpose_h<<<dim3(32, 15), tb, 0, s1>>>(Wfc, hwfc, 1024, 460);
    cudaEventRecord(eWfc, s1);

    // ---- s2: graph structure (overlaps MLP/projection) ----
    zero_int2<<<(N + 255) / 256, 256, 0, s2>>>(deg, cur, N);
    build_edges<<<(ET + 255) / 256, 256, 0, s2>>>(ei, src, dst, deg, E, N);
    scan_excl<<<1, 1024, 0, s2>>>(deg, off, N);
    fill_csr<<<(ET + 255) / 256, 256, 0, s2>>>(dst, off, cur, csr, ET);
    cudaEventRecord(eGraph, s2);

    // ---- s0: main chain ----
    f2h<<<(Nx * 200 + 255) / 256, 256, 0, s0>>>((const float2*)x, (__half2*)hxin, Nx * 200);
    f2h<<<(Nc * 512 + 255) / 256, 256, 0, s0>>>((const float2*)emb, (__half2*)hxc, Nc * 512);

    cudaStreamWaitEvent(s0, eW1, 0);
    gemm_h<true, true><<<gemm_grid(Nx, 512), 256, H_SMEM, s0>>>(hxin, hw1, b1, hxh, Nx, 512, 400);

    cudaStreamWaitEvent(s0, eW2, 0);
    gemm_h<false, true><<<gemm_grid(Nx, 1024), 256, H_SMEM, s0>>>(hxh, hw2, b2, hxc + (size_t)Nc * 1024, Nx, 1024, 512);

    cudaStreamWaitEvent(s0, eWlr, 0);
    gemm_h<false, true><<<gemm_grid(N, 8192), 256, H_SMEM, s0>>>(hxc, hwlr, bcat, hxlr, N, 8192, 1024);

    cudaStreamWaitEvent(s0, eGraph, 0);
    gat_fused<<<N, 256, 0, s0>>>(hxlr, off, csr, src, att, gb, alpha, houtm, N);

    cudaStreamWaitEvent(s0, eWfc, 0);
    gemm_h<false, false><<<gemm_grid(N, 460), 256, H_SMEM, s0>>>(houtm, hwfc, bfc, (float*)d_out, N, 460, 1024);

    copy_f4<<<(Nx * 115 + 255) / 256, 256, 0, s0>>>((const float4*)exps,
                                                    (float4*)((float*)d_out + (size_t)N * 460),
                                                    Nx * 115);

    // forks are joined into s0 via eWfc (covers all of s1) and eGraph (all of s2)
    cudaEventDestroy(eFork);
    cudaEventDestroy(eW1);
    cudaEventDestroy(eW2);
    cudaEventDestroy(eWlr);
    cudaEventDestroy(eWfc);
    cudaEventDestroy(eGraph);
    cudaStreamDestroy(s1);
    cudaStreamDestroy(s2);
}